// round 8
// baseline (speedup 1.0000x reference)
#include <cuda_runtime.h>
#include <cuda_bf16.h>
#include <math.h>
#include <cstdint>

// Problem constants
#define BATCH 2
#define SEQ   2048
#define HID   4096
#define NH    32
#define NKV   8
#define HD    128
#define TOKENS (BATCH*SEQ)          // 4096
#define QROW (NH*HD)                // 4096
#define KROW (NKV*HD)               // 1024
#define QKVW (QROW + 2*KROW)        // 6144
#define VCOL0 (QROW + KROW)         // 5120 : first V column in fused qkv

// ---------------- scratch (no cudaMalloc allowed) ----------------
__device__ float g_qkv[(size_t)TOKENS * QKVW];   // q|k|v per token
__device__ float g_attn[(size_t)TOKENS * QROW];
__device__ float g_hsc[(size_t)TOKENS * HID];
__device__ float g_wqkv[(size_t)QKVW * HID];
__device__ float g_woc[(size_t)HID * QROW];

// ---------------- helpers ----------------
__device__ __forceinline__ uint32_t sa(const void* p) {
    return (uint32_t)__cvta_generic_to_shared(p);
}
__device__ __forceinline__ void cp_async16(uint32_t s, const void* g) {
    asm volatile("cp.async.cg.shared.global [%0], [%1], 16;" :: "r"(s), "l"(g));
}
__device__ __forceinline__ void cp_commit() {
    asm volatile("cp.async.commit_group;" ::: "memory");
}
template <int N>
__device__ __forceinline__ void cp_wait() {
    asm volatile("cp.async.wait_group %0;" :: "n"(N) : "memory");
}
__device__ __forceinline__ void ldsm4(uint32_t& r0, uint32_t& r1, uint32_t& r2,
                                      uint32_t& r3, uint32_t addr) {
    asm volatile("ldmatrix.sync.aligned.m8n8.x4.shared.b16 {%0,%1,%2,%3}, [%4];"
                 : "=r"(r0), "=r"(r1), "=r"(r2), "=r"(r3) : "r"(addr));
}
__device__ __forceinline__ void mma_tf32(float* d, const uint32_t* a, const uint32_t* b) {
    asm volatile(
        "mma.sync.aligned.m16n8k8.row.col.f32.tf32.tf32.f32 "
        "{%0,%1,%2,%3}, {%4,%5,%6,%7}, {%8,%9}, {%0,%1,%2,%3};"
        : "+f"(d[0]), "+f"(d[1]), "+f"(d[2]), "+f"(d[3])
        : "r"(a[0]), "r"(a[1]), "r"(a[2]), "r"(a[3]), "r"(b[0]), "r"(b[1]));
}
__device__ __forceinline__ float tf32rn(float x) {
    uint32_t u;
    asm("cvt.rn.tf32.f32 %0, %1;" : "=r"(u) : "f"(x));
    return __uint_as_float(u);
}
__device__ __forceinline__ float ex2(float x) {
    float y;
    asm("ex2.approx.ftz.f32 %0, %1;" : "=f"(y) : "f"(x));
    return y;
}

// =================================================================
// Rounding kernels (split so QKV GEMM lands at launch index 3)
// =================================================================
#define NHS4 ((long)TOKENS * HID / 4)
#define NQ4  ((long)QROW * HID / 4)
#define NK4  ((long)KROW * HID / 4)
#define NWQKV4 (NQ4 + 2*NK4)

__global__ __launch_bounds__(256)
void round_hs_kernel(const float4* __restrict__ in, float4* __restrict__ out)
{
    long base = ((long)blockIdx.x * 256 + threadIdx.x) * 4;
#pragma unroll
    for (int j = 0; j < 4; j++) {
        long i = base + j;
        if (i >= NHS4) return;
        float4 v = in[i];
        out[i] = make_float4(tf32rn(v.x), tf32rn(v.y), tf32rn(v.z), tf32rn(v.w));
    }
}

__global__ __launch_bounds__(256)
void round_wqkv_kernel(const float4* __restrict__ wq, const float4* __restrict__ wk,
                       const float4* __restrict__ wv, float4* __restrict__ wqkv)
{
    long base = ((long)blockIdx.x * 256 + threadIdx.x) * 4;
#pragma unroll
    for (int j = 0; j < 4; j++) {
        long i = base + j;
        if (i >= NWQKV4) return;
        float4 v;
        if (i < NQ4)            v = wq[i];
        else if (i < NQ4 + NK4) v = wk[i - NQ4];
        else                    v = wv[i - NQ4 - NK4];
        wqkv[i] = make_float4(tf32rn(v.x), tf32rn(v.y), tf32rn(v.z), tf32rn(v.w));
    }
}

__global__ __launch_bounds__(256)
void round_wo_kernel(const float4* __restrict__ in, float4* __restrict__ out)
{
    long base = ((long)blockIdx.x * 256 + threadIdx.x) * 4;
#pragma unroll
    for (int j = 0; j < 4; j++) {
        long i = base + j;
        if (i >= NQ4) return;
        float4 v = in[i];
        out[i] = make_float4(tf32rn(v.x), tf32rn(v.y), tf32rn(v.z), tf32rn(v.w));
    }
}

// =================================================================
// tf32 mma.sync GEMM (ldmatrix fragments):  C[m,n] = sum_k A[m,k]*B[n,k]
// Columns with n0 >= roundColStart get tf32-rounded in the epilogue.
// =================================================================
#define GSTRIDE 36
#define A_FLOATS (128 * GSTRIDE)
#define B_FLOATS (256 * GSTRIDE)
#define STAGE_FLOATS (A_FLOATS + B_FLOATS)
#define GEMM_SMEM (2 * STAGE_FLOATS * 4)

__global__ __launch_bounds__(256, 1)
void gemm_mma(const float* __restrict__ A, const float* __restrict__ B,
              float* __restrict__ C, int M, int N, int K, int roundColStart)
{
    extern __shared__ float sm[];

    const int tid = threadIdx.x;
    const int wid = tid >> 5;
    const int lane = tid & 31;
    const int g = lane >> 2;
    const int t = lane & 3;
    const int lr = lane & 7;
    const int lm = lane >> 3;
    const int wm = wid & 1;
    const int wn = wid >> 1;
    const int m0 = blockIdx.y * 128;
    const int n0 = blockIdx.x * 256;

    const float* Ag = A + (size_t)m0 * K;
    const float* Bg = B + (size_t)n0 * K;

    auto load_stage = [&](int kt, int st) {
        float* As = sm + st * STAGE_FLOATS;
        float* Bs = As + A_FLOATS;
        const float* ap = Ag + kt * 32;
        const float* bp = Bg + kt * 32;
#pragma unroll
        for (int r = 0; r < 4; r++) {
            int c = r * 256 + tid;
            int row = c >> 3;
            int c4  = (c & 7) * 4;
            cp_async16(sa(As + row * GSTRIDE + c4), ap + (size_t)row * K + c4);
        }
#pragma unroll
        for (int r = 0; r < 8; r++) {
            int c = r * 256 + tid;
            int row = c >> 3;
            int c4  = (c & 7) * 4;
            cp_async16(sa(Bs + row * GSTRIDE + c4), bp + (size_t)row * K + c4);
        }
        cp_commit();
    };

    float d[4][8][4];
#pragma unroll
    for (int mi = 0; mi < 4; mi++)
#pragma unroll
        for (int ni = 0; ni < 8; ni++)
#pragma unroll
            for (int r = 0; r < 4; r++) d[mi][ni][r] = 0.0f;

    const uint32_t aoff = (uint32_t)(((wm * 64 + (lm & 1) * 8 + lr) * GSTRIDE
                                      + (lm >> 1) * 4) * 4);
    const uint32_t boff = (uint32_t)(((wn * 64 + (lm >> 1) * 8 + lr) * GSTRIDE
                                      + (lm & 1) * 4) * 4);

    const int NT = K / 32;
    load_stage(0, 0);

    for (int kt = 0; kt < NT; kt++) {
        const int st = kt & 1;
        if (kt + 1 < NT) { load_stage(kt + 1, st ^ 1); cp_wait<1>(); }
        else             { cp_wait<0>(); }
        __syncthreads();

        const uint32_t As = sa(sm + st * STAGE_FLOATS);
        const uint32_t Bs = As + A_FLOATS * 4;

#pragma unroll
        for (int kk = 0; kk < 4; kk++) {
            uint32_t a[4][4], b[8][2];
#pragma unroll
            for (int mi = 0; mi < 4; mi++)
                ldsm4(a[mi][0], a[mi][1], a[mi][2], a[mi][3],
                      As + aoff + (uint32_t)((mi * 16 * GSTRIDE + kk * 8) * 4));
#pragma unroll
            for (int p = 0; p < 4; p++)
                ldsm4(b[2*p][0], b[2*p][1], b[2*p+1][0], b[2*p+1][1],
                      Bs + boff + (uint32_t)((p * 16 * GSTRIDE + kk * 8) * 4));
#pragma unroll
            for (int mi = 0; mi < 4; mi++)
#pragma unroll
                for (int ni = 0; ni < 8; ni++)
                    mma_tf32(d[mi][ni], a[mi], b[ni]);
        }
        __syncthreads();
    }

    // ---- epilogue (coalesced; optional tf32 rounding) ----
    const bool rnd = (n0 >= roundColStart);
#pragma unroll
    for (int mi = 0; mi < 4; mi++) {
        const int r0 = m0 + wm * 64 + mi * 16 + g;
        float* c0p = C + (size_t)r0 * N + n0 + wn * 64;
        float* c1p = c0p + (size_t)8 * N;
        if (rnd) {
#pragma unroll
            for (int ni = 0; ni < 8; ni++) {
                *(float2*)(c0p + ni * 8 + t * 2) =
                    make_float2(tf32rn(d[mi][ni][0]), tf32rn(d[mi][ni][1]));
                *(float2*)(c1p + ni * 8 + t * 2) =
                    make_float2(tf32rn(d[mi][ni][2]), tf32rn(d[mi][ni][3]));
            }
        } else {
#pragma unroll
            for (int ni = 0; ni < 8; ni++) {
                *(float2*)(c0p + ni * 8 + t * 2) = make_float2(d[mi][ni][0], d[mi][ni][1]);
                *(float2*)(c1p + ni * 8 + t * 2) = make_float2(d[mi][ni][2], d[mi][ni][3]);
            }
        }
    }
}

// =================================================================
// Fused RoPE for Q (slots 0-31, scale qscale) and K (slots 32-39).
// In place on g_qkv; output tf32-rounded.
// =================================================================
__global__ __launch_bounds__(256)
void rope_qk_kernel(float* __restrict__ qkv, const float* __restrict__ cosb,
                    const float* __restrict__ sinb, float qscale)
{
    long idx = (long)blockIdx.x * blockDim.x + threadIdx.x;
    long total = (long)TOKENS * (NH + NKV) * 64;
    if (idx >= total) return;
    int d = (int)(idx & 63);
    long t2 = idx >> 6;
    int slot = (int)(t2 % (NH + NKV));
    long tok = t2 / (NH + NKV);
    float scale = (slot < NH) ? qscale : 1.0f;
    int off = (slot < NH) ? slot * HD : QROW + (slot - NH) * HD;
    float* row = qkv + tok * QKVW + off;
    float c0 = cosb[tok * HD + d];
    float s0 = sinb[tok * HD + d];
    float c1 = cosb[tok * HD + d + 64];
    float s1 = sinb[tok * HD + d + 64];
    float a = row[d];
    float b = row[d + 64];
    row[d]      = tf32rn((a * c0 - b * s0) * scale);
    row[d + 64] = tf32rn((b * c1 + a * s1) * scale);
}

// =================================================================
// Tensor-core flash attention (causal, GQA 4:1), tf32 mma.sync.
// ldmatrix for Q/K fragments; scalar conflict-free loads for P/V.
// K and V read from fused qkv (token stride 6144), V row-major.
// CTA: 128 queries x 1 head; 8 warps x 16 query rows; key tile 64.
// Smem: 2 stages x (Ks[64][132] + Vs[64][136]) + Ps[128][68].
// =================================================================
#define AKS 132
#define AVSTR 136
#define APS 68
#define KS_FLOATS (64 * AKS)
#define VS_FLOATS (64 * AVSTR)
#define STG_FLOATS (KS_FLOATS + VS_FLOATS)
#define PS_OFF (2 * STG_FLOATS)
#define ATTN_SMEM ((PS_OFF + 128 * APS) * 4)  // 172032 B

__global__ __launch_bounds__(256, 1)
void attn_mma(const float* __restrict__ QKV, float* __restrict__ O)
{
    extern __shared__ float sm[];

    const int tid = threadIdx.x;
    const int wid = tid >> 5;
    const int lane = tid & 31;
    const int g = lane >> 2;
    const int t = lane & 3;
    const int lr = lane & 7;
    const int lm = lane >> 3;

    const int bh = blockIdx.y;
    const int b   = bh >> 5;
    const int h   = bh & 31;
    const int kvh = h >> 2;
    const int qt  = (int)(gridDim.x - 1 - blockIdx.x);
    const int q0  = qt * 128;

    const float* Qb = QKV + (size_t)b * SEQ * QKVW + h * HD;
    const float* Kb = QKV + (size_t)b * SEQ * QKVW + QROW + kvh * HD;
    const float* Vb = QKV + (size_t)b * SEQ * QKVW + VCOL0 + kvh * HD;

    // ---- stage Q into smem (stage-0 region), fragments via ldmatrix ----
    {
#pragma unroll
        for (int it = 0; it < 16; it++) {
            int idx = it * 256 + tid;
            int row = idx >> 5;
            int c4  = (idx & 31) * 4;
            cp_async16(sa(sm + row * AKS + c4),
                       Qb + (size_t)(q0 + row) * QKVW + c4);
        }
        cp_commit();
        cp_wait<0>();
        __syncthreads();
    }

    uint32_t qa[16][4];
    {
        const uint32_t qoff = sa(sm) +
            (uint32_t)(((wid * 16 + (lm & 1) * 8 + lr) * AKS + (lm >> 1) * 4) * 4);
#pragma unroll
        for (int kk = 0; kk < 16; kk++)
            ldsm4(qa[kk][0], qa[kk][1], qa[kk][2], qa[kk][3], qoff + kk * 32);
    }
    __syncthreads();

    const int qbase = q0 + wid * 16;

    float m0r = -1e30f, m1r = -1e30f, l0r = 0.0f, l1r = 0.0f;
    float oa[16][4];
#pragma unroll
    for (int ni = 0; ni < 16; ni++)
#pragma unroll
        for (int r = 0; r < 4; r++) oa[ni][r] = 0.0f;

    const int nkt = qt * 2 + 2;

    auto load_kv = [&](int kt, int st) {
        float* Ks = sm + st * STG_FLOATS;
        float* Vs = Ks + KS_FLOATS;
        const int k0 = kt * 64;
#pragma unroll
        for (int it = 0; it < 8; it++) {
            int idx = it * 256 + tid;
            int row = idx >> 5;
            int c4  = (idx & 31) * 4;
            cp_async16(sa(Ks + row * AKS + c4),
                       Kb + (size_t)(k0 + row) * QKVW + c4);
        }
#pragma unroll
        for (int it = 0; it < 8; it++) {
            int idx = it * 256 + tid;
            int row = idx >> 5;
            int c4  = (idx & 31) * 4;
            cp_async16(sa(Vs + row * AVSTR + c4),
                       Vb + (size_t)(k0 + row) * QKVW + c4);
        }
        cp_commit();
    };

    load_kv(0, 0);
    load_kv(1, 1);

    const uint32_t kboff = (uint32_t)((((lm >> 1) * 8 + lr) * AKS + (lm & 1) * 4) * 4);

    for (int kt = 0; kt < nkt; kt++) {
        const int st = kt & 1;
        const int k0 = kt * 64;
        if (kt + 1 < nkt) cp_wait<1>();
        else              cp_wait<0>();
        __syncthreads();

        const uint32_t KsA = sa(sm + st * STG_FLOATS);
        const float* Vs = sm + st * STG_FLOATS + KS_FLOATS;

        // ---- scores S = Q K^T (p-outer to minimize live temps) ----
        float sc[8][4];
#pragma unroll
        for (int ni = 0; ni < 8; ni++)
#pragma unroll
            for (int r = 0; r < 4; r++) sc[ni][r] = 0.0f;

#pragma unroll
        for (int p = 0; p < 4; p++) {
#pragma unroll
            for (int kk = 0; kk < 16; kk++) {
                uint32_t b0, b1, b2, b3;
                ldsm4(b0, b1, b2, b3,
                      KsA + kboff + (uint32_t)((p * 16 * AKS + kk * 8) * 4));
                uint32_t bf0[2] = {b0, b1};
                uint32_t bf1[2] = {b2, b3};
                mma_tf32(sc[2*p],     qa[kk], bf0);
                mma_tf32(sc[2*p + 1], qa[kk], bf1);
            }
        }

        // ---- causal mask ----
        if (k0 + 63 > qbase) {
#pragma unroll
            for (int ni = 0; ni < 8; ni++) {
                int c0 = k0 + ni * 8 + 2 * t;
                int r0 = qbase + g;
                if (c0 > r0)     sc[ni][0] = -1e30f;
                if (c0 + 1 > r0) sc[ni][1] = -1e30f;
                if (c0 > r0 + 8)     sc[ni][2] = -1e30f;
                if (c0 + 1 > r0 + 8) sc[ni][3] = -1e30f;
            }
        }

        // ---- online softmax ----
        float mx0 = -1e30f, mx1 = -1e30f;
#pragma unroll
        for (int ni = 0; ni < 8; ni++) {
            mx0 = fmaxf(mx0, fmaxf(sc[ni][0], sc[ni][1]));
            mx1 = fmaxf(mx1, fmaxf(sc[ni][2], sc[ni][3]));
        }
        mx0 = fmaxf(mx0, __shfl_xor_sync(0xffffffffu, mx0, 1));
        mx0 = fmaxf(mx0, __shfl_xor_sync(0xffffffffu, mx0, 2));
        mx1 = fmaxf(mx1, __shfl_xor_sync(0xffffffffu, mx1, 1));
        mx1 = fmaxf(mx1, __shfl_xor_sync(0xffffffffu, mx1, 2));

        float mn0 = fmaxf(m0r, mx0);
        float mn1 = fmaxf(m1r, mx1);
        float cr0 = ex2(m0r - mn0);
        float cr1 = ex2(m1r - mn1);
        m0r = mn0; m1r = mn1;

        float rs0 = 0.0f, rs1 = 0.0f;
        float* pw0 = sm + PS_OFF + (wid * 16 + g) * APS;
        float* pw1 = pw0 + 8 * APS;
#pragma unroll
        for (int ni = 0; ni < 8; ni++) {
            float p0 = ex2(sc[ni][0] - mn0);
            float p1 = ex2(sc[ni][1] - mn0);
            float p2 = ex2(sc[ni][2] - mn1);
            float p3 = ex2(sc[ni][3] - mn1);
            rs0 += p0 + p1;
            rs1 += p2 + p3;
            *(float2*)(pw0 + ni * 8 + 2 * t) = make_float2(tf32rn(p0), tf32rn(p1));
            *(float2*)(pw1 + ni * 8 + 2 * t) = make_float2(tf32rn(p2), tf32rn(p3));
        }
        rs0 += __shfl_xor_sync(0xffffffffu, rs0, 1);
        rs0 += __shfl_xor_sync(0xffffffffu, rs0, 2);
        rs1 += __shfl_xor_sync(0xffffffffu, rs1, 1);
        rs1 += __shfl_xor_sync(0xffffffffu, rs1, 2);
        l0r = l0r * cr0 + rs0;
        l1r = l1r * cr1 + rs1;

#pragma unroll
        for (int ni = 0; ni < 16; ni++) {
            oa[ni][0] *= cr0; oa[ni][1] *= cr0;
            oa[ni][2] *= cr1; oa[ni][3] *= cr1;
        }
        __syncwarp();

        // ---- O += P V : scalar conflict-free fragment loads ----
#pragma unroll
        for (int kk = 0; kk < 8; kk++) {
            uint32_t a[4];
            const float* ap = sm + PS_OFF + (wid * 16 + g) * APS + kk * 8 + t;
            a[0] = __float_as_uint(ap[0]);
            a[1] = __float_as_uint(ap[8 * APS]);
            a[2] = __float_as_uint(ap[4]);
            a[3] = __float_as_uint(ap[8 * APS + 4]);
#pragma unroll
            for (int ni = 0; ni < 16; ni++) {
                uint32_t bfr[2];
                const float* bp = Vs + (kk * 8 + t) * AVSTR + ni * 8 + g;
                bfr[0] = __float_as_uint(bp[0]);
                bfr[1] = __float_as_uint(bp[4 * AVSTR]);
                mma_tf32(oa[ni], a, bfr);
            }
        }
        __syncthreads();
        if (kt + 2 < nkt) load_kv(kt + 2, st);
    }

    // ---- epilogue: O / l, tf32-rounded for the O-projection ----
    float inv0 = 1.0f / l0r;
    float inv1 = 1.0f / l1r;
    float* o0 = O + (size_t)((size_t)b * SEQ + qbase + g) * QROW + h * HD;
    float* o1 = o0 + (size_t)8 * QROW;
#pragma unroll
    for (int ni = 0; ni < 16; ni++) {
        *(float2*)(o0 + ni * 8 + 2 * t) =
            make_float2(tf32rn(oa[ni][0] * inv0), tf32rn(oa[ni][1] * inv0));
        *(float2*)(o1 + ni * 8 + 2 * t) =
            make_float2(tf32rn(oa[ni][2] * inv1), tf32rn(oa[ni][3] * inv1));
    }
}

// =================================================================
extern "C" void kernel_launch(void* const* d_in, const int* in_sizes, int n_in,
                              void* d_out, int out_size)
{
    const float* hs   = (const float*)d_in[0];
    const float* cosb = (const float*)d_in[1];
    const float* sinb = (const float*)d_in[2];
    const float* wq   = (const float*)d_in[3];
    const float* wk   = (const float*)d_in[4];
    const float* wv   = (const float*)d_in[5];
    const float* wo   = (const float*)d_in[6];
    float* out = (float*)d_out;

    float *qkv, *attn, *hsc, *wqkv, *woc;
    cudaGetSymbolAddress((void**)&qkv,  g_qkv);
    cudaGetSymbolAddress((void**)&attn, g_attn);
    cudaGetSymbolAddress((void**)&hsc,  g_hsc);
    cudaGetSymbolAddress((void**)&wqkv, g_wqkv);
    cudaGetSymbolAddress((void**)&woc,  g_woc);

    cudaFuncSetAttribute(gemm_mma, cudaFuncAttributeMaxDynamicSharedMemorySize, GEMM_SMEM);
    cudaFuncSetAttribute(attn_mma, cudaFuncAttributeMaxDynamicSharedMemorySize, ATTN_SMEM);

    // L0-L2: tf32 rounding (hs, wq|wk|wv, wo)
    round_hs_kernel<<<(unsigned)((NHS4 + 1023) / 1024), 256>>>(
        (const float4*)hs, (float4*)hsc);
    round_wqkv_kernel<<<(unsigned)((NWQKV4 + 1023) / 1024), 256>>>(
        (const float4*)wq, (const float4*)wk, (const float4*)wv, (float4*)wqkv);
    round_wo_kernel<<<(unsigned)((NQ4 + 1023) / 1024), 256>>>(
        (const float4*)wo, (float4*)woc);

    // L3: fused QKV projection (profiled); V columns tf32-rounded in epilogue
    gemm_mma<<<dim3(QKVW / 256, TOKENS / 128), 256, GEMM_SMEM>>>(
        hsc, wqkv, qkv, TOKENS, QKVW, HID, VCOL0);

    // L4: fused RoPE Q+K (Q scale folds 1/sqrt(128)*log2(e))
    const float qscale = 0.08838834764831845f * 1.4426950408889634f;
    rope_qk_kernel<<<(TOKENS * (NH + NKV) * 64) / 256, 256>>>(qkv, cosb, sinb, qscale);

    // L5: flash attention
    attn_mma<<<dim3(SEQ / 128, BATCH * NH), 256, ATTN_SMEM>>>(qkv, attn);

    // L6: output projection (no epilogue rounding)
    gemm_mma<<<dim3(HID / 256, TOKENS / 128), 256, GEMM_SMEM>>>(
        attn, woc, out, TOKENS, HID, QROW, 1 << 30);
}

// round 9
// speedup vs baseline: 1.0371x; 1.0371x over previous
#include <cuda_runtime.h>
#include <cuda_bf16.h>
#include <math.h>
#include <cstdint>

// Problem constants
#define BATCH 2
#define SEQ   2048
#define HID   4096
#define NH    32
#define NKV   8
#define HD    128
#define TOKENS (BATCH*SEQ)          // 4096
#define QROW (NH*HD)                // 4096
#define KROW (NKV*HD)               // 1024
#define QKVW (QROW + 2*KROW)        // 6144
#define VCOL0 (QROW + KROW)         // 5120 : first V column in fused qkv

// ---------------- scratch (no cudaMalloc allowed) ----------------
__device__ float g_qkv[(size_t)TOKENS * QKVW];   // q|k|v per token
__device__ float g_attn[(size_t)TOKENS * QROW];
__device__ float g_hsc[(size_t)TOKENS * HID];
__device__ float g_wqkv[(size_t)QKVW * HID];
__device__ float g_woc[(size_t)HID * QROW];

// ---------------- helpers ----------------
__device__ __forceinline__ uint32_t sa(const void* p) {
    return (uint32_t)__cvta_generic_to_shared(p);
}
__device__ __forceinline__ void cp_async16(uint32_t s, const void* g) {
    asm volatile("cp.async.cg.shared.global [%0], [%1], 16;" :: "r"(s), "l"(g));
}
__device__ __forceinline__ void cp_commit() {
    asm volatile("cp.async.commit_group;" ::: "memory");
}
template <int N>
__device__ __forceinline__ void cp_wait() {
    asm volatile("cp.async.wait_group %0;" :: "n"(N) : "memory");
}
__device__ __forceinline__ void ldsm4(uint32_t& r0, uint32_t& r1, uint32_t& r2,
                                      uint32_t& r3, uint32_t addr) {
    asm volatile("ldmatrix.sync.aligned.m8n8.x4.shared.b16 {%0,%1,%2,%3}, [%4];"
                 : "=r"(r0), "=r"(r1), "=r"(r2), "=r"(r3) : "r"(addr));
}
__device__ __forceinline__ void mma_tf32(float* d, const uint32_t* a, const uint32_t* b) {
    asm volatile(
        "mma.sync.aligned.m16n8k8.row.col.f32.tf32.tf32.f32 "
        "{%0,%1,%2,%3}, {%4,%5,%6,%7}, {%8,%9}, {%0,%1,%2,%3};"
        : "+f"(d[0]), "+f"(d[1]), "+f"(d[2]), "+f"(d[3])
        : "r"(a[0]), "r"(a[1]), "r"(a[2]), "r"(a[3]), "r"(b[0]), "r"(b[1]));
}
__device__ __forceinline__ float tf32rn(float x) {
    uint32_t u;
    asm("cvt.rn.tf32.f32 %0, %1;" : "=r"(u) : "f"(x));
    return __uint_as_float(u);
}
__device__ __forceinline__ float ex2(float x) {
    float y;
    asm("ex2.approx.ftz.f32 %0, %1;" : "=f"(y) : "f"(x));
    return y;
}

// =================================================================
// L0: fused rounding of hs + all weights, 4 float4 per thread (MLP)
// =================================================================
#define NHS4 ((long)TOKENS * HID / 4)
#define NQ4  ((long)QROW * HID / 4)
#define NK4  ((long)KROW * HID / 4)
#define NALL4 (NHS4 + NQ4 + 2*NK4 + NQ4)

__global__ __launch_bounds__(256)
void round_all_kernel(const float4* __restrict__ hs, const float4* __restrict__ wq,
                      const float4* __restrict__ wk, const float4* __restrict__ wv,
                      const float4* __restrict__ wo,
                      float4* __restrict__ hsc, float4* __restrict__ wqkv,
                      float4* __restrict__ woc)
{
    long base = ((long)blockIdx.x * 256 + threadIdx.x) * 4;
#pragma unroll
    for (int j = 0; j < 4; j++) {
        long i = base + j;
        if (i >= NALL4) return;
        float4 v;
        float4* dst;
        if (i < NHS4) { v = hs[i]; dst = hsc + i; }
        else {
            long w = i - NHS4;
            if (w < NQ4)              { v = wq[w];               dst = wqkv + w; }
            else if (w < NQ4 + NK4)   { v = wk[w - NQ4];         dst = wqkv + w; }
            else if (w < NQ4 + 2*NK4) { v = wv[w - NQ4 - NK4];   dst = wqkv + w; }
            else                      { v = wo[w - NQ4 - 2*NK4]; dst = woc + (w - NQ4 - 2*NK4); }
        }
        *dst = make_float4(tf32rn(v.x), tf32rn(v.y), tf32rn(v.z), tf32rn(v.w));
    }
}

// =================================================================
// tf32 mma.sync GEMM, 512 threads / 16 warps, warp tile 32x64.
// C[m,n] = sum_k A[m,k]*B[n,k]; tile 128(M) x 256(N), BK=32.
// Columns with n0 >= roundColStart get tf32-rounded in the epilogue.
// =================================================================
#define GSTRIDE 36
#define A_FLOATS (128 * GSTRIDE)
#define B_FLOATS (256 * GSTRIDE)
#define STAGE_FLOATS (A_FLOATS + B_FLOATS)
#define GEMM_SMEM (2 * STAGE_FLOATS * 4)

__global__ __launch_bounds__(512, 1)
void gemm_mma(const float* __restrict__ A, const float* __restrict__ B,
              float* __restrict__ C, int M, int N, int K, int roundColStart)
{
    extern __shared__ float sm[];

    const int tid = threadIdx.x;
    const int wid = tid >> 5;
    const int lane = tid & 31;
    const int g = lane >> 2;
    const int t = lane & 3;
    const int lr = lane & 7;
    const int lm = lane >> 3;
    const int wm = wid & 3;          // 4 m-groups of 32 rows
    const int wn = wid >> 2;         // 4 n-groups of 64 cols
    const int m0 = blockIdx.y * 128;
    const int n0 = blockIdx.x * 256;

    const float* Ag = A + (size_t)m0 * K;
    const float* Bg = B + (size_t)n0 * K;

    auto load_stage = [&](int kt, int st) {
        float* As = sm + st * STAGE_FLOATS;
        float* Bs = As + A_FLOATS;
        const float* ap = Ag + kt * 32;
        const float* bp = Bg + kt * 32;
#pragma unroll
        for (int r = 0; r < 2; r++) {            // A: 1024 float4 chunks
            int c = r * 512 + tid;
            int row = c >> 3;
            int c4  = (c & 7) * 4;
            cp_async16(sa(As + row * GSTRIDE + c4), ap + (size_t)row * K + c4);
        }
#pragma unroll
        for (int r = 0; r < 4; r++) {            // B: 2048 float4 chunks
            int c = r * 512 + tid;
            int row = c >> 3;
            int c4  = (c & 7) * 4;
            cp_async16(sa(Bs + row * GSTRIDE + c4), bp + (size_t)row * K + c4);
        }
        cp_commit();
    };

    float d[2][8][4];
#pragma unroll
    for (int mi = 0; mi < 2; mi++)
#pragma unroll
        for (int ni = 0; ni < 8; ni++)
#pragma unroll
            for (int r = 0; r < 4; r++) d[mi][ni][r] = 0.0f;

    const uint32_t aoff = (uint32_t)(((wm * 32 + (lm & 1) * 8 + lr) * GSTRIDE
                                      + (lm >> 1) * 4) * 4);
    const uint32_t boff = (uint32_t)(((wn * 64 + (lm >> 1) * 8 + lr) * GSTRIDE
                                      + (lm & 1) * 4) * 4);

    const int NT = K / 32;
    load_stage(0, 0);

    for (int kt = 0; kt < NT; kt++) {
        const int st = kt & 1;
        if (kt + 1 < NT) { load_stage(kt + 1, st ^ 1); cp_wait<1>(); }
        else             { cp_wait<0>(); }
        __syncthreads();

        const uint32_t As = sa(sm + st * STAGE_FLOATS);
        const uint32_t Bs = As + A_FLOATS * 4;

#pragma unroll
        for (int kk = 0; kk < 4; kk++) {
            uint32_t a[2][4];
#pragma unroll
            for (int mi = 0; mi < 2; mi++)
                ldsm4(a[mi][0], a[mi][1], a[mi][2], a[mi][3],
                      As + aoff + (uint32_t)((mi * 16 * GSTRIDE + kk * 8) * 4));
#pragma unroll
            for (int p = 0; p < 4; p++) {
                uint32_t b0, b1, b2, b3;
                ldsm4(b0, b1, b2, b3,
                      Bs + boff + (uint32_t)((p * 16 * GSTRIDE + kk * 8) * 4));
                uint32_t bf0[2] = {b0, b1};
                uint32_t bf1[2] = {b2, b3};
                mma_tf32(d[0][2*p],     a[0], bf0);
                mma_tf32(d[0][2*p + 1], a[0], bf1);
                mma_tf32(d[1][2*p],     a[1], bf0);
                mma_tf32(d[1][2*p + 1], a[1], bf1);
            }
        }
        __syncthreads();
    }

    // ---- epilogue (coalesced; optional tf32 rounding) ----
    const bool rnd = (n0 >= roundColStart);
#pragma unroll
    for (int mi = 0; mi < 2; mi++) {
        const int r0 = m0 + wm * 32 + mi * 16 + g;
        float* c0p = C + (size_t)r0 * N + n0 + wn * 64;
        float* c1p = c0p + (size_t)8 * N;
        if (rnd) {
#pragma unroll
            for (int ni = 0; ni < 8; ni++) {
                *(float2*)(c0p + ni * 8 + t * 2) =
                    make_float2(tf32rn(d[mi][ni][0]), tf32rn(d[mi][ni][1]));
                *(float2*)(c1p + ni * 8 + t * 2) =
                    make_float2(tf32rn(d[mi][ni][2]), tf32rn(d[mi][ni][3]));
            }
        } else {
#pragma unroll
            for (int ni = 0; ni < 8; ni++) {
                *(float2*)(c0p + ni * 8 + t * 2) = make_float2(d[mi][ni][0], d[mi][ni][1]);
                *(float2*)(c1p + ni * 8 + t * 2) = make_float2(d[mi][ni][2], d[mi][ni][3]);
            }
        }
    }
}

// =================================================================
// Fused RoPE for Q (slots 0-31, scale qscale) and K (slots 32-39).
// In place on g_qkv; output tf32-rounded.
// =================================================================
__global__ __launch_bounds__(256)
void rope_qk_kernel(float* __restrict__ qkv, const float* __restrict__ cosb,
                    const float* __restrict__ sinb, float qscale)
{
    long idx = (long)blockIdx.x * blockDim.x + threadIdx.x;
    long total = (long)TOKENS * (NH + NKV) * 64;
    if (idx >= total) return;
    int d = (int)(idx & 63);
    long t2 = idx >> 6;
    int slot = (int)(t2 % (NH + NKV));
    long tok = t2 / (NH + NKV);
    float scale = (slot < NH) ? qscale : 1.0f;
    int off = (slot < NH) ? slot * HD : QROW + (slot - NH) * HD;
    float* row = qkv + tok * QKVW + off;
    float c0 = cosb[tok * HD + d];
    float s0 = sinb[tok * HD + d];
    float c1 = cosb[tok * HD + d + 64];
    float s1 = sinb[tok * HD + d + 64];
    float a = row[d];
    float b = row[d + 64];
    row[d]      = tf32rn((a * c0 - b * s0) * scale);
    row[d + 64] = tf32rn((b * c1 + a * s1) * scale);
}

// =================================================================
// Tensor-core flash attention (causal, GQA 4:1), tf32 mma.sync.
// ldmatrix for Q/K fragments; scalar conflict-free loads for P/V.
// K and V read from fused qkv (token stride 6144), V row-major.
// CTA: 128 queries x 1 head; 8 warps x 16 query rows; key tile 64.
// =================================================================
#define AKS 132
#define AVSTR 136
#define APS 68
#define KS_FLOATS (64 * AKS)
#define VS_FLOATS (64 * AVSTR)
#define STG_FLOATS (KS_FLOATS + VS_FLOATS)
#define PS_OFF (2 * STG_FLOATS)
#define ATTN_SMEM ((PS_OFF + 128 * APS) * 4)  // 172032 B

__global__ __launch_bounds__(256, 1)
void attn_mma(const float* __restrict__ QKV, float* __restrict__ O)
{
    extern __shared__ float sm[];

    const int tid = threadIdx.x;
    const int wid = tid >> 5;
    const int lane = tid & 31;
    const int g = lane >> 2;
    const int t = lane & 3;
    const int lr = lane & 7;
    const int lm = lane >> 3;

    const int bh = blockIdx.y;
    const int b   = bh >> 5;
    const int h   = bh & 31;
    const int kvh = h >> 2;
    const int qt  = (int)(gridDim.x - 1 - blockIdx.x);
    const int q0  = qt * 128;

    const float* Qb = QKV + (size_t)b * SEQ * QKVW + h * HD;
    const float* Kb = QKV + (size_t)b * SEQ * QKVW + QROW + kvh * HD;
    const float* Vb = QKV + (size_t)b * SEQ * QKVW + VCOL0 + kvh * HD;

    // ---- stage Q into smem (stage-0 region), fragments via ldmatrix ----
    {
#pragma unroll
        for (int it = 0; it < 16; it++) {
            int idx = it * 256 + tid;
            int row = idx >> 5;
            int c4  = (idx & 31) * 4;
            cp_async16(sa(sm + row * AKS + c4),
                       Qb + (size_t)(q0 + row) * QKVW + c4);
        }
        cp_commit();
        cp_wait<0>();
        __syncthreads();
    }

    uint32_t qa[16][4];
    {
        const uint32_t qoff = sa(sm) +
            (uint32_t)(((wid * 16 + (lm & 1) * 8 + lr) * AKS + (lm >> 1) * 4) * 4);
#pragma unroll
        for (int kk = 0; kk < 16; kk++)
            ldsm4(qa[kk][0], qa[kk][1], qa[kk][2], qa[kk][3], qoff + kk * 32);
    }
    __syncthreads();

    const int qbase = q0 + wid * 16;

    float m0r = -1e30f, m1r = -1e30f, l0r = 0.0f, l1r = 0.0f;
    float oa[16][4];
#pragma unroll
    for (int ni = 0; ni < 16; ni++)
#pragma unroll
        for (int r = 0; r < 4; r++) oa[ni][r] = 0.0f;

    const int nkt = qt * 2 + 2;

    auto load_kv = [&](int kt, int st) {
        float* Ks = sm + st * STG_FLOATS;
        float* Vs = Ks + KS_FLOATS;
        const int k0 = kt * 64;
#pragma unroll
        for (int it = 0; it < 8; it++) {
            int idx = it * 256 + tid;
            int row = idx >> 5;
            int c4  = (idx & 31) * 4;
            cp_async16(sa(Ks + row * AKS + c4),
                       Kb + (size_t)(k0 + row) * QKVW + c4);
        }
#pragma unroll
        for (int it = 0; it < 8; it++) {
            int idx = it * 256 + tid;
            int row = idx >> 5;
            int c4  = (idx & 31) * 4;
            cp_async16(sa(Vs + row * AVSTR + c4),
                       Vb + (size_t)(k0 + row) * QKVW + c4);
        }
        cp_commit();
    };

    load_kv(0, 0);
    load_kv(1, 1);

    const uint32_t kboff = (uint32_t)((((lm >> 1) * 8 + lr) * AKS + (lm & 1) * 4) * 4);

    for (int kt = 0; kt < nkt; kt++) {
        const int st = kt & 1;
        const int k0 = kt * 64;
        if (kt + 1 < nkt) cp_wait<1>();
        else              cp_wait<0>();
        __syncthreads();

        const uint32_t KsA = sa(sm + st * STG_FLOATS);
        const float* Vs = sm + st * STG_FLOATS + KS_FLOATS;

        // ---- scores S = Q K^T (p-outer to minimize live temps) ----
        float sc[8][4];
#pragma unroll
        for (int ni = 0; ni < 8; ni++)
#pragma unroll
            for (int r = 0; r < 4; r++) sc[ni][r] = 0.0f;

#pragma unroll
        for (int p = 0; p < 4; p++) {
#pragma unroll
            for (int kk = 0; kk < 16; kk++) {
                uint32_t b0, b1, b2, b3;
                ldsm4(b0, b1, b2, b3,
                      KsA + kboff + (uint32_t)((p * 16 * AKS + kk * 8) * 4));
                uint32_t bf0[2] = {b0, b1};
                uint32_t bf1[2] = {b2, b3};
                mma_tf32(sc[2*p],     qa[kk], bf0);
                mma_tf32(sc[2*p + 1], qa[kk], bf1);
            }
        }

        // ---- causal mask ----
        if (k0 + 63 > qbase) {
#pragma unroll
            for (int ni = 0; ni < 8; ni++) {
                int c0 = k0 + ni * 8 + 2 * t;
                int r0 = qbase + g;
                if (c0 > r0)     sc[ni][0] = -1e30f;
                if (c0 + 1 > r0) sc[ni][1] = -1e30f;
                if (c0 > r0 + 8)     sc[ni][2] = -1e30f;
                if (c0 + 1 > r0 + 8) sc[ni][3] = -1e30f;
            }
        }

        // ---- online softmax ----
        float mx0 = -1e30f, mx1 = -1e30f;
#pragma unroll
        for (int ni = 0; ni < 8; ni++) {
            mx0 = fmaxf(mx0, fmaxf(sc[ni][0], sc[ni][1]));
            mx1 = fmaxf(mx1, fmaxf(sc[ni][2], sc[ni][3]));
        }
        mx0 = fmaxf(mx0, __shfl_xor_sync(0xffffffffu, mx0, 1));
        mx0 = fmaxf(mx0, __shfl_xor_sync(0xffffffffu, mx0, 2));
        mx1 = fmaxf(mx1, __shfl_xor_sync(0xffffffffu, mx1, 1));
        mx1 = fmaxf(mx1, __shfl_xor_sync(0xffffffffu, mx1, 2));

        float mn0 = fmaxf(m0r, mx0);
        float mn1 = fmaxf(m1r, mx1);
        float cr0 = ex2(m0r - mn0);
        float cr1 = ex2(m1r - mn1);
        m0r = mn0; m1r = mn1;

        float rs0 = 0.0f, rs1 = 0.0f;
        float* pw0 = sm + PS_OFF + (wid * 16 + g) * APS;
        float* pw1 = pw0 + 8 * APS;
#pragma unroll
        for (int ni = 0; ni < 8; ni++) {
            float p0 = ex2(sc[ni][0] - mn0);
            float p1 = ex2(sc[ni][1] - mn0);
            float p2 = ex2(sc[ni][2] - mn1);
            float p3 = ex2(sc[ni][3] - mn1);
            rs0 += p0 + p1;
            rs1 += p2 + p3;
            *(float2*)(pw0 + ni * 8 + 2 * t) = make_float2(tf32rn(p0), tf32rn(p1));
            *(float2*)(pw1 + ni * 8 + 2 * t) = make_float2(tf32rn(p2), tf32rn(p3));
        }
        rs0 += __shfl_xor_sync(0xffffffffu, rs0, 1);
        rs0 += __shfl_xor_sync(0xffffffffu, rs0, 2);
        rs1 += __shfl_xor_sync(0xffffffffu, rs1, 1);
        rs1 += __shfl_xor_sync(0xffffffffu, rs1, 2);
        l0r = l0r * cr0 + rs0;
        l1r = l1r * cr1 + rs1;

#pragma unroll
        for (int ni = 0; ni < 16; ni++) {
            oa[ni][0] *= cr0; oa[ni][1] *= cr0;
            oa[ni][2] *= cr1; oa[ni][3] *= cr1;
        }
        __syncwarp();

        // ---- O += P V : scalar conflict-free fragment loads ----
#pragma unroll
        for (int kk = 0; kk < 8; kk++) {
            uint32_t a[4];
            const float* ap = sm + PS_OFF + (wid * 16 + g) * APS + kk * 8 + t;
            a[0] = __float_as_uint(ap[0]);
            a[1] = __float_as_uint(ap[8 * APS]);
            a[2] = __float_as_uint(ap[4]);
            a[3] = __float_as_uint(ap[8 * APS + 4]);
#pragma unroll
            for (int ni = 0; ni < 16; ni++) {
                uint32_t bfr[2];
                const float* bp = Vs + (kk * 8 + t) * AVSTR + ni * 8 + g;
                bfr[0] = __float_as_uint(bp[0]);
                bfr[1] = __float_as_uint(bp[4 * AVSTR]);
                mma_tf32(oa[ni], a, bfr);
            }
        }
        __syncthreads();
        if (kt + 2 < nkt) load_kv(kt + 2, st);
    }

    // ---- epilogue: O / l, tf32-rounded for the O-projection ----
    float inv0 = 1.0f / l0r;
    float inv1 = 1.0f / l1r;
    float* o0 = O + (size_t)((size_t)b * SEQ + qbase + g) * QROW + h * HD;
    float* o1 = o0 + (size_t)8 * QROW;
#pragma unroll
    for (int ni = 0; ni < 16; ni++) {
        *(float2*)(o0 + ni * 8 + 2 * t) =
            make_float2(tf32rn(oa[ni][0] * inv0), tf32rn(oa[ni][1] * inv0));
        *(float2*)(o1 + ni * 8 + 2 * t) =
            make_float2(tf32rn(oa[ni][2] * inv1), tf32rn(oa[ni][3] * inv1));
    }
}

// =================================================================
extern "C" void kernel_launch(void* const* d_in, const int* in_sizes, int n_in,
                              void* d_out, int out_size)
{
    const float* hs   = (const float*)d_in[0];
    const float* cosb = (const float*)d_in[1];
    const float* sinb = (const float*)d_in[2];
    const float* wq   = (const float*)d_in[3];
    const float* wk   = (const float*)d_in[4];
    const float* wv   = (const float*)d_in[5];
    const float* wo   = (const float*)d_in[6];
    float* out = (float*)d_out;

    float *qkv, *attn, *hsc, *wqkv, *woc;
    cudaGetSymbolAddress((void**)&qkv,  g_qkv);
    cudaGetSymbolAddress((void**)&attn, g_attn);
    cudaGetSymbolAddress((void**)&hsc,  g_hsc);
    cudaGetSymbolAddress((void**)&wqkv, g_wqkv);
    cudaGetSymbolAddress((void**)&woc,  g_woc);

    cudaFuncSetAttribute(gemm_mma, cudaFuncAttributeMaxDynamicSharedMemorySize, GEMM_SMEM);
    cudaFuncSetAttribute(attn_mma, cudaFuncAttributeMaxDynamicSharedMemorySize, ATTN_SMEM);

    // L0: fused tf32 rounding (hs + wq|wk|wv + wo)
    long nblk = (NALL4 + 1023) / 1024;
    round_all_kernel<<<(unsigned)nblk, 256>>>(
        (const float4*)hs, (const float4*)wq, (const float4*)wk,
        (const float4*)wv, (const float4*)wo,
        (float4*)hsc, (float4*)wqkv, (float4*)woc);

    // L1: fused QKV projection (512 threads); V columns tf32-rounded
    gemm_mma<<<dim3(QKVW / 256, TOKENS / 128), 512, GEMM_SMEM>>>(
        hsc, wqkv, qkv, TOKENS, QKVW, HID, VCOL0);

    // L2: fused RoPE Q+K (Q scale folds 1/sqrt(128)*log2(e))
    const float qscale = 0.08838834764831845f * 1.4426950408889634f;
    rope_qk_kernel<<<(TOKENS * (NH + NKV) * 64) / 256, 256>>>(qkv, cosb, sinb, qscale);

    // L3: flash attention (profiled: launch index 3)
    attn_mma<<<dim3(SEQ / 128, BATCH * NH), 256, ATTN_SMEM>>>(qkv, attn);

    // L4: output projection (no epilogue rounding)
    gemm_mma<<<dim3(HID / 256, TOKENS / 128), 512, GEMM_SMEM>>>(
        attn, woc, out, TOKENS, HID, QROW, 1 << 30);
}

// round 10
// speedup vs baseline: 1.0916x; 1.0526x over previous
#include <cuda_runtime.h>
#include <cuda_bf16.h>
#include <math.h>
#include <cstdint>

// Problem constants
#define BATCH 2
#define SEQ   2048
#define HID   4096
#define NH    32
#define NKV   8
#define HD    128
#define TOKENS (BATCH*SEQ)          // 4096
#define QROW (NH*HD)                // 4096
#define KROW (NKV*HD)               // 1024
#define QKVW (QROW + 2*KROW)        // 6144
#define VCOL0 (QROW + KROW)         // 5120 : first V column in fused qkv

// ---------------- scratch (no cudaMalloc allowed) ----------------
__device__ float g_qkv[(size_t)TOKENS * QKVW];   // q|k|v per token
__device__ float g_attn[(size_t)TOKENS * QROW];
__device__ float g_hsc[(size_t)TOKENS * HID];
__device__ float g_wqkv[(size_t)QKVW * HID];
__device__ float g_woc[(size_t)HID * QROW];

// ---------------- helpers ----------------
__device__ __forceinline__ uint32_t sa(const void* p) {
    return (uint32_t)__cvta_generic_to_shared(p);
}
__device__ __forceinline__ void cp_async16(uint32_t s, const void* g) {
    asm volatile("cp.async.cg.shared.global [%0], [%1], 16;" :: "r"(s), "l"(g));
}
__device__ __forceinline__ void cp_commit() {
    asm volatile("cp.async.commit_group;" ::: "memory");
}
template <int N>
__device__ __forceinline__ void cp_wait() {
    asm volatile("cp.async.wait_group %0;" :: "n"(N) : "memory");
}
__device__ __forceinline__ void ldsm4(uint32_t& r0, uint32_t& r1, uint32_t& r2,
                                      uint32_t& r3, uint32_t addr) {
    asm volatile("ldmatrix.sync.aligned.m8n8.x4.shared.b16 {%0,%1,%2,%3}, [%4];"
                 : "=r"(r0), "=r"(r1), "=r"(r2), "=r"(r3) : "r"(addr));
}
__device__ __forceinline__ void mma_tf32(float* d, const uint32_t* a, const uint32_t* b) {
    asm volatile(
        "mma.sync.aligned.m16n8k8.row.col.f32.tf32.tf32.f32 "
        "{%0,%1,%2,%3}, {%4,%5,%6,%7}, {%8,%9}, {%0,%1,%2,%3};"
        : "+f"(d[0]), "+f"(d[1]), "+f"(d[2]), "+f"(d[3])
        : "r"(a[0]), "r"(a[1]), "r"(a[2]), "r"(a[3]), "r"(b[0]), "r"(b[1]));
}
__device__ __forceinline__ float tf32rn(float x) {
    uint32_t u;
    asm("cvt.rn.tf32.f32 %0, %1;" : "=r"(u) : "f"(x));
    return __uint_as_float(u);
}
__device__ __forceinline__ float ex2(float x) {
    float y;
    asm("ex2.approx.ftz.f32 %0, %1;" : "=f"(y) : "f"(x));
    return y;
}

// =================================================================
// L0: fused rounding of hs + all weights, 4 float4 per thread (MLP)
// =================================================================
#define NHS4 ((long)TOKENS * HID / 4)
#define NQ4  ((long)QROW * HID / 4)
#define NK4  ((long)KROW * HID / 4)
#define NALL4 (NHS4 + NQ4 + 2*NK4 + NQ4)

__global__ __launch_bounds__(256)
void round_all_kernel(const float4* __restrict__ hs, const float4* __restrict__ wq,
                      const float4* __restrict__ wk, const float4* __restrict__ wv,
                      const float4* __restrict__ wo,
                      float4* __restrict__ hsc, float4* __restrict__ wqkv,
                      float4* __restrict__ woc)
{
    long base = ((long)blockIdx.x * 256 + threadIdx.x) * 4;
#pragma unroll
    for (int j = 0; j < 4; j++) {
        long i = base + j;
        if (i >= NALL4) return;
        float4 v;
        float4* dst;
        if (i < NHS4) { v = hs[i]; dst = hsc + i; }
        else {
            long w = i - NHS4;
            if (w < NQ4)              { v = wq[w];               dst = wqkv + w; }
            else if (w < NQ4 + NK4)   { v = wk[w - NQ4];         dst = wqkv + w; }
            else if (w < NQ4 + 2*NK4) { v = wv[w - NQ4 - NK4];   dst = wqkv + w; }
            else                      { v = wo[w - NQ4 - 2*NK4]; dst = woc + (w - NQ4 - 2*NK4); }
        }
        *dst = make_float4(tf32rn(v.x), tf32rn(v.y), tf32rn(v.z), tf32rn(v.w));
    }
}

// =================================================================
// tf32 mma.sync GEMM, 512 threads / 16 warps, warp tile 32x64.
// 3-stage cp.async pipeline, ONE barrier per mainloop iteration.
// C[m,n] = sum_k A[m,k]*B[n,k]; tile 128(M) x 256(N), BK=32.
// Columns with n0 >= roundColStart get tf32-rounded in the epilogue.
// =================================================================
#define GSTRIDE 36
#define A_FLOATS (128 * GSTRIDE)
#define B_FLOATS (256 * GSTRIDE)
#define STAGE_FLOATS (A_FLOATS + B_FLOATS)       // 13824 floats = 55296 B
#define GEMM_STAGES 3
#define GEMM_SMEM (GEMM_STAGES * STAGE_FLOATS * 4)  // 165888 B

__global__ __launch_bounds__(512, 1)
void gemm_mma(const float* __restrict__ A, const float* __restrict__ B,
              float* __restrict__ C, int M, int N, int K, int roundColStart)
{
    extern __shared__ float sm[];

    const int tid = threadIdx.x;
    const int wid = tid >> 5;
    const int lane = tid & 31;
    const int g = lane >> 2;
    const int t = lane & 3;
    const int lr = lane & 7;
    const int lm = lane >> 3;
    const int wm = wid & 3;          // 4 m-groups of 32 rows
    const int wn = wid >> 2;         // 4 n-groups of 64 cols
    const int m0 = blockIdx.y * 128;
    const int n0 = blockIdx.x * 256;

    const float* Ag = A + (size_t)m0 * K;
    const float* Bg = B + (size_t)n0 * K;

    auto load_stage = [&](int kt, int slot) {
        float* As = sm + slot * STAGE_FLOATS;
        float* Bs = As + A_FLOATS;
        const float* ap = Ag + kt * 32;
        const float* bp = Bg + kt * 32;
#pragma unroll
        for (int r = 0; r < 2; r++) {            // A: 1024 float4 chunks
            int c = r * 512 + tid;
            int row = c >> 3;
            int c4  = (c & 7) * 4;
            cp_async16(sa(As + row * GSTRIDE + c4), ap + (size_t)row * K + c4);
        }
#pragma unroll
        for (int r = 0; r < 4; r++) {            // B: 2048 float4 chunks
            int c = r * 512 + tid;
            int row = c >> 3;
            int c4  = (c & 7) * 4;
            cp_async16(sa(Bs + row * GSTRIDE + c4), bp + (size_t)row * K + c4);
        }
        cp_commit();
    };

    float d[2][8][4];
#pragma unroll
    for (int mi = 0; mi < 2; mi++)
#pragma unroll
        for (int ni = 0; ni < 8; ni++)
#pragma unroll
            for (int r = 0; r < 4; r++) d[mi][ni][r] = 0.0f;

    const uint32_t aoff = (uint32_t)(((wm * 32 + (lm & 1) * 8 + lr) * GSTRIDE
                                      + (lm >> 1) * 4) * 4);
    const uint32_t boff = (uint32_t)(((wn * 64 + (lm >> 1) * 8 + lr) * GSTRIDE
                                      + (lm & 1) * 4) * 4);

    const int NT = K / 32;
    load_stage(0, 0);
    load_stage(1, 1);

    int slot = 0;
    for (int kt = 0; kt < NT; kt++) {
        // tile kt was issued 2 iterations ago; allow the newer one in flight
        if (kt + 1 < NT) cp_wait<1>();
        else             cp_wait<0>();
        __syncthreads();   // all warps done with compute of iter kt-1

        // prefetch tile kt+2 into the slot consumed at iter kt-1 (safe post-barrier)
        if (kt + 2 < NT) {
            int ps = slot + 2; if (ps >= GEMM_STAGES) ps -= GEMM_STAGES;
            load_stage(kt + 2, ps);
        }

        const uint32_t As = sa(sm + slot * STAGE_FLOATS);
        const uint32_t Bs = As + A_FLOATS * 4;

#pragma unroll
        for (int kk = 0; kk < 4; kk++) {
            uint32_t a[2][4];
#pragma unroll
            for (int mi = 0; mi < 2; mi++)
                ldsm4(a[mi][0], a[mi][1], a[mi][2], a[mi][3],
                      As + aoff + (uint32_t)((mi * 16 * GSTRIDE + kk * 8) * 4));
#pragma unroll
            for (int p = 0; p < 4; p++) {
                uint32_t b0, b1, b2, b3;
                ldsm4(b0, b1, b2, b3,
                      Bs + boff + (uint32_t)((p * 16 * GSTRIDE + kk * 8) * 4));
                uint32_t bf0[2] = {b0, b1};
                uint32_t bf1[2] = {b2, b3};
                mma_tf32(d[0][2*p],     a[0], bf0);
                mma_tf32(d[0][2*p + 1], a[0], bf1);
                mma_tf32(d[1][2*p],     a[1], bf0);
                mma_tf32(d[1][2*p + 1], a[1], bf1);
            }
        }
        if (++slot == GEMM_STAGES) slot = 0;
    }

    // ---- epilogue (coalesced; optional tf32 rounding) ----
    const bool rnd = (n0 >= roundColStart);
#pragma unroll
    for (int mi = 0; mi < 2; mi++) {
        const int r0 = m0 + wm * 32 + mi * 16 + g;
        float* c0p = C + (size_t)r0 * N + n0 + wn * 64;
        float* c1p = c0p + (size_t)8 * N;
        if (rnd) {
#pragma unroll
            for (int ni = 0; ni < 8; ni++) {
                *(float2*)(c0p + ni * 8 + t * 2) =
                    make_float2(tf32rn(d[mi][ni][0]), tf32rn(d[mi][ni][1]));
                *(float2*)(c1p + ni * 8 + t * 2) =
                    make_float2(tf32rn(d[mi][ni][2]), tf32rn(d[mi][ni][3]));
            }
        } else {
#pragma unroll
            for (int ni = 0; ni < 8; ni++) {
                *(float2*)(c0p + ni * 8 + t * 2) = make_float2(d[mi][ni][0], d[mi][ni][1]);
                *(float2*)(c1p + ni * 8 + t * 2) = make_float2(d[mi][ni][2], d[mi][ni][3]);
            }
        }
    }
}

// =================================================================
// Fused RoPE for Q (slots 0-31, scale qscale) and K (slots 32-39).
// In place on g_qkv; output tf32-rounded.
// =================================================================
__global__ __launch_bounds__(256)
void rope_qk_kernel(float* __restrict__ qkv, const float* __restrict__ cosb,
                    const float* __restrict__ sinb, float qscale)
{
    long idx = (long)blockIdx.x * blockDim.x + threadIdx.x;
    long total = (long)TOKENS * (NH + NKV) * 64;
    if (idx >= total) return;
    int d = (int)(idx & 63);
    long t2 = idx >> 6;
    int slot = (int)(t2 % (NH + NKV));
    long tok = t2 / (NH + NKV);
    float scale = (slot < NH) ? qscale : 1.0f;
    int off = (slot < NH) ? slot * HD : QROW + (slot - NH) * HD;
    float* row = qkv + tok * QKVW + off;
    float c0 = cosb[tok * HD + d];
    float s0 = sinb[tok * HD + d];
    float c1 = cosb[tok * HD + d + 64];
    float s1 = sinb[tok * HD + d + 64];
    float a = row[d];
    float b = row[d + 64];
    row[d]      = tf32rn((a * c0 - b * s0) * scale);
    row[d + 64] = tf32rn((b * c1 + a * s1) * scale);
}

// =================================================================
// Tensor-core flash attention (causal, GQA 4:1), tf32 mma.sync.
// ldmatrix for Q/K fragments; scalar conflict-free loads for P/V.
// K and V read from fused qkv (token stride 6144), V row-major.
// CTA: 128 queries x 1 head; 8 warps x 16 query rows; key tile 64.
// =================================================================
#define AKS 132
#define AVSTR 136
#define APS 68
#define KS_FLOATS (64 * AKS)
#define VS_FLOATS (64 * AVSTR)
#define STG_FLOATS (KS_FLOATS + VS_FLOATS)
#define PS_OFF (2 * STG_FLOATS)
#define ATTN_SMEM ((PS_OFF + 128 * APS) * 4)  // 172032 B

__global__ __launch_bounds__(256, 1)
void attn_mma(const float* __restrict__ QKV, float* __restrict__ O)
{
    extern __shared__ float sm[];

    const int tid = threadIdx.x;
    const int wid = tid >> 5;
    const int lane = tid & 31;
    const int g = lane >> 2;
    const int t = lane & 3;
    const int lr = lane & 7;
    const int lm = lane >> 3;

    const int bh = blockIdx.y;
    const int b   = bh >> 5;
    const int h   = bh & 31;
    const int kvh = h >> 2;
    const int qt  = (int)(gridDim.x - 1 - blockIdx.x);
    const int q0  = qt * 128;

    const float* Qb = QKV + (size_t)b * SEQ * QKVW + h * HD;
    const float* Kb = QKV + (size_t)b * SEQ * QKVW + QROW + kvh * HD;
    const float* Vb = QKV + (size_t)b * SEQ * QKVW + VCOL0 + kvh * HD;

    // ---- stage Q into smem (stage-0 region), fragments via ldmatrix ----
    {
#pragma unroll
        for (int it = 0; it < 16; it++) {
            int idx = it * 256 + tid;
            int row = idx >> 5;
            int c4  = (idx & 31) * 4;
            cp_async16(sa(sm + row * AKS + c4),
                       Qb + (size_t)(q0 + row) * QKVW + c4);
        }
        cp_commit();
        cp_wait<0>();
        __syncthreads();
    }

    uint32_t qa[16][4];
    {
        const uint32_t qoff = sa(sm) +
            (uint32_t)(((wid * 16 + (lm & 1) * 8 + lr) * AKS + (lm >> 1) * 4) * 4);
#pragma unroll
        for (int kk = 0; kk < 16; kk++)
            ldsm4(qa[kk][0], qa[kk][1], qa[kk][2], qa[kk][3], qoff + kk * 32);
    }
    __syncthreads();

    const int qbase = q0 + wid * 16;

    float m0r = -1e30f, m1r = -1e30f, l0r = 0.0f, l1r = 0.0f;
    float oa[16][4];
#pragma unroll
    for (int ni = 0; ni < 16; ni++)
#pragma unroll
        for (int r = 0; r < 4; r++) oa[ni][r] = 0.0f;

    const int nkt = qt * 2 + 2;

    auto load_kv = [&](int kt, int st) {
        float* Ks = sm + st * STG_FLOATS;
        float* Vs = Ks + KS_FLOATS;
        const int k0 = kt * 64;
#pragma unroll
        for (int it = 0; it < 8; it++) {
            int idx = it * 256 + tid;
            int row = idx >> 5;
            int c4  = (idx & 31) * 4;
            cp_async16(sa(Ks + row * AKS + c4),
                       Kb + (size_t)(k0 + row) * QKVW + c4);
        }
#pragma unroll
        for (int it = 0; it < 8; it++) {
            int idx = it * 256 + tid;
            int row = idx >> 5;
            int c4  = (idx & 31) * 4;
            cp_async16(sa(Vs + row * AVSTR + c4),
                       Vb + (size_t)(k0 + row) * QKVW + c4);
        }
        cp_commit();
    };

    load_kv(0, 0);
    load_kv(1, 1);

    const uint32_t kboff = (uint32_t)((((lm >> 1) * 8 + lr) * AKS + (lm & 1) * 4) * 4);

    for (int kt = 0; kt < nkt; kt++) {
        const int st = kt & 1;
        const int k0 = kt * 64;
        if (kt + 1 < nkt) cp_wait<1>();
        else              cp_wait<0>();
        __syncthreads();

        const uint32_t KsA = sa(sm + st * STG_FLOATS);
        const float* Vs = sm + st * STG_FLOATS + KS_FLOATS;

        // ---- scores S = Q K^T (p-outer to minimize live temps) ----
        float sc[8][4];
#pragma unroll
        for (int ni = 0; ni < 8; ni++)
#pragma unroll
            for (int r = 0; r < 4; r++) sc[ni][r] = 0.0f;

#pragma unroll
        for (int p = 0; p < 4; p++) {
#pragma unroll
            for (int kk = 0; kk < 16; kk++) {
                uint32_t b0, b1, b2, b3;
                ldsm4(b0, b1, b2, b3,
                      KsA + kboff + (uint32_t)((p * 16 * AKS + kk * 8) * 4));
                uint32_t bf0[2] = {b0, b1};
                uint32_t bf1[2] = {b2, b3};
                mma_tf32(sc[2*p],     qa[kk], bf0);
                mma_tf32(sc[2*p + 1], qa[kk], bf1);
            }
        }

        // ---- causal mask ----
        if (k0 + 63 > qbase) {
#pragma unroll
            for (int ni = 0; ni < 8; ni++) {
                int c0 = k0 + ni * 8 + 2 * t;
                int r0 = qbase + g;
                if (c0 > r0)     sc[ni][0] = -1e30f;
                if (c0 + 1 > r0) sc[ni][1] = -1e30f;
                if (c0 > r0 + 8)     sc[ni][2] = -1e30f;
                if (c0 + 1 > r0 + 8) sc[ni][3] = -1e30f;
            }
        }

        // ---- online softmax ----
        float mx0 = -1e30f, mx1 = -1e30f;
#pragma unroll
        for (int ni = 0; ni < 8; ni++) {
            mx0 = fmaxf(mx0, fmaxf(sc[ni][0], sc[ni][1]));
            mx1 = fmaxf(mx1, fmaxf(sc[ni][2], sc[ni][3]));
        }
        mx0 = fmaxf(mx0, __shfl_xor_sync(0xffffffffu, mx0, 1));
        mx0 = fmaxf(mx0, __shfl_xor_sync(0xffffffffu, mx0, 2));
        mx1 = fmaxf(mx1, __shfl_xor_sync(0xffffffffu, mx1, 1));
        mx1 = fmaxf(mx1, __shfl_xor_sync(0xffffffffu, mx1, 2));

        float mn0 = fmaxf(m0r, mx0);
        float mn1 = fmaxf(m1r, mx1);
        float cr0 = ex2(m0r - mn0);
        float cr1 = ex2(m1r - mn1);
        m0r = mn0; m1r = mn1;

        float rs0 = 0.0f, rs1 = 0.0f;
        float* pw0 = sm + PS_OFF + (wid * 16 + g) * APS;
        float* pw1 = pw0 + 8 * APS;
#pragma unroll
        for (int ni = 0; ni < 8; ni++) {
            float p0 = ex2(sc[ni][0] - mn0);
            float p1 = ex2(sc[ni][1] - mn0);
            float p2 = ex2(sc[ni][2] - mn1);
            float p3 = ex2(sc[ni][3] - mn1);
            rs0 += p0 + p1;
            rs1 += p2 + p3;
            *(float2*)(pw0 + ni * 8 + 2 * t) = make_float2(tf32rn(p0), tf32rn(p1));
            *(float2*)(pw1 + ni * 8 + 2 * t) = make_float2(tf32rn(p2), tf32rn(p3));
        }
        rs0 += __shfl_xor_sync(0xffffffffu, rs0, 1);
        rs0 += __shfl_xor_sync(0xffffffffu, rs0, 2);
        rs1 += __shfl_xor_sync(0xffffffffu, rs1, 1);
        rs1 += __shfl_xor_sync(0xffffffffu, rs1, 2);
        l0r = l0r * cr0 + rs0;
        l1r = l1r * cr1 + rs1;

#pragma unroll
        for (int ni = 0; ni < 16; ni++) {
            oa[ni][0] *= cr0; oa[ni][1] *= cr0;
            oa[ni][2] *= cr1; oa[ni][3] *= cr1;
        }
        __syncwarp();

        // ---- O += P V : scalar conflict-free fragment loads ----
#pragma unroll
        for (int kk = 0; kk < 8; kk++) {
            uint32_t a[4];
            const float* ap = sm + PS_OFF + (wid * 16 + g) * APS + kk * 8 + t;
            a[0] = __float_as_uint(ap[0]);
            a[1] = __float_as_uint(ap[8 * APS]);
            a[2] = __float_as_uint(ap[4]);
            a[3] = __float_as_uint(ap[8 * APS + 4]);
#pragma unroll
            for (int ni = 0; ni < 16; ni++) {
                uint32_t bfr[2];
                const float* bp = Vs + (kk * 8 + t) * AVSTR + ni * 8 + g;
                bfr[0] = __float_as_uint(bp[0]);
                bfr[1] = __float_as_uint(bp[4 * AVSTR]);
                mma_tf32(oa[ni], a, bfr);
            }
        }
        __syncthreads();
        if (kt + 2 < nkt) load_kv(kt + 2, st);
    }

    // ---- epilogue: O / l, tf32-rounded for the O-projection ----
    float inv0 = 1.0f / l0r;
    float inv1 = 1.0f / l1r;
    float* o0 = O + (size_t)((size_t)b * SEQ + qbase + g) * QROW + h * HD;
    float* o1 = o0 + (size_t)8 * QROW;
#pragma unroll
    for (int ni = 0; ni < 16; ni++) {
        *(float2*)(o0 + ni * 8 + 2 * t) =
            make_float2(tf32rn(oa[ni][0] * inv0), tf32rn(oa[ni][1] * inv0));
        *(float2*)(o1 + ni * 8 + 2 * t) =
            make_float2(tf32rn(oa[ni][2] * inv1), tf32rn(oa[ni][3] * inv1));
    }
}

// =================================================================
extern "C" void kernel_launch(void* const* d_in, const int* in_sizes, int n_in,
                              void* d_out, int out_size)
{
    const float* hs   = (const float*)d_in[0];
    const float* cosb = (const float*)d_in[1];
    const float* sinb = (const float*)d_in[2];
    const float* wq   = (const float*)d_in[3];
    const float* wk   = (const float*)d_in[4];
    const float* wv   = (const float*)d_in[5];
    const float* wo   = (const float*)d_in[6];
    float* out = (float*)d_out;

    float *qkv, *attn, *hsc, *wqkv, *woc;
    cudaGetSymbolAddress((void**)&qkv,  g_qkv);
    cudaGetSymbolAddress((void**)&attn, g_attn);
    cudaGetSymbolAddress((void**)&hsc,  g_hsc);
    cudaGetSymbolAddress((void**)&wqkv, g_wqkv);
    cudaGetSymbolAddress((void**)&woc,  g_woc);

    cudaFuncSetAttribute(gemm_mma, cudaFuncAttributeMaxDynamicSharedMemorySize, GEMM_SMEM);
    cudaFuncSetAttribute(attn_mma, cudaFuncAttributeMaxDynamicSharedMemorySize, ATTN_SMEM);

    // L0: fused tf32 rounding (hs + wq|wk|wv + wo)
    long nblk = (NALL4 + 1023) / 1024;
    round_all_kernel<<<(unsigned)nblk, 256>>>(
        (const float4*)hs, (const float4*)wq, (const float4*)wk,
        (const float4*)wv, (const float4*)wo,
        (float4*)hsc, (float4*)wqkv, (float4*)woc);

    // L1: fused QKV projection (3-stage pipeline); V columns tf32-rounded
    gemm_mma<<<dim3(QKVW / 256, TOKENS / 128), 512, GEMM_SMEM>>>(
        hsc, wqkv, qkv, TOKENS, QKVW, HID, VCOL0);

    // L2: fused RoPE Q+K (Q scale folds 1/sqrt(128)*log2(e))
    const float qscale = 0.08838834764831845f * 1.4426950408889634f;
    rope_qk_kernel<<<(TOKENS * (NH + NKV) * 64) / 256, 256>>>(qkv, cosb, sinb, qscale);

    // L3: flash attention (profiled: launch index 3)
    attn_mma<<<dim3(SEQ / 128, BATCH * NH), 256, ATTN_SMEM>>>(qkv, attn);

    // L4: output projection (no epilogue rounding)
    gemm_mma<<<dim3(HID / 256, TOKENS / 128), 512, GEMM_SMEM>>>(
        attn, woc, out, TOKENS, HID, QROW, 1 << 30);
}

// round 11
// speedup vs baseline: 1.2473x; 1.1426x over previous
#include <cuda_runtime.h>
#include <cuda_bf16.h>
#include <math.h>
#include <cstdint>

// Problem constants
#define BATCH 2
#define SEQ   2048
#define HID   4096
#define NH    32
#define NKV   8
#define HD    128
#define TOKENS (BATCH*SEQ)          // 4096
#define QROW (NH*HD)                // 4096
#define KROW (NKV*HD)               // 1024
#define QKVW (QROW + 2*KROW)        // 6144
#define VCOL0 (QROW + KROW)         // 5120 : first V column in fused qkv

// ---------------- scratch (no cudaMalloc allowed) ----------------
__device__ float g_qkv[(size_t)TOKENS * QKVW];   // q|k|v per token
__device__ float g_attn[(size_t)TOKENS * QROW];
__device__ float g_hsc[(size_t)TOKENS * HID];
__device__ float g_wqkv[(size_t)QKVW * HID];
__device__ float g_woc[(size_t)HID * QROW];

// ---------------- helpers ----------------
__device__ __forceinline__ uint32_t sa(const void* p) {
    return (uint32_t)__cvta_generic_to_shared(p);
}
__device__ __forceinline__ void cp_async16(uint32_t s, const void* g) {
    asm volatile("cp.async.cg.shared.global [%0], [%1], 16;" :: "r"(s), "l"(g));
}
__device__ __forceinline__ void cp_commit() {
    asm volatile("cp.async.commit_group;" ::: "memory");
}
template <int N>
__device__ __forceinline__ void cp_wait() {
    asm volatile("cp.async.wait_group %0;" :: "n"(N) : "memory");
}
__device__ __forceinline__ void ldsm4(uint32_t& r0, uint32_t& r1, uint32_t& r2,
                                      uint32_t& r3, uint32_t addr) {
    asm volatile("ldmatrix.sync.aligned.m8n8.x4.shared.b16 {%0,%1,%2,%3}, [%4];"
                 : "=r"(r0), "=r"(r1), "=r"(r2), "=r"(r3) : "r"(addr));
}
__device__ __forceinline__ void mma_tf32(float* d, const uint32_t* a, const uint32_t* b) {
    asm volatile(
        "mma.sync.aligned.m16n8k8.row.col.f32.tf32.tf32.f32 "
        "{%0,%1,%2,%3}, {%4,%5,%6,%7}, {%8,%9}, {%0,%1,%2,%3};"
        : "+f"(d[0]), "+f"(d[1]), "+f"(d[2]), "+f"(d[3])
        : "r"(a[0]), "r"(a[1]), "r"(a[2]), "r"(a[3]), "r"(b[0]), "r"(b[1]));
}
__device__ __forceinline__ float tf32rn(float x) {
    uint32_t u;
    asm("cvt.rn.tf32.f32 %0, %1;" : "=r"(u) : "f"(x));
    return __uint_as_float(u);
}
__device__ __forceinline__ float ex2(float x) {
    float y;
    asm("ex2.approx.ftz.f32 %0, %1;" : "=f"(y) : "f"(x));
    return y;
}

// =================================================================
// Rounding kernels (split so QKV GEMM lands at launch index 3)
// =================================================================
#define NHS4 ((long)TOKENS * HID / 4)
#define NQ4  ((long)QROW * HID / 4)
#define NK4  ((long)KROW * HID / 4)
#define NWQKV4 (NQ4 + 2*NK4)

__global__ __launch_bounds__(256)
void round_hs_kernel(const float4* __restrict__ in, float4* __restrict__ out)
{
    long base = ((long)blockIdx.x * 256 + threadIdx.x) * 4;
#pragma unroll
    for (int j = 0; j < 4; j++) {
        long i = base + j;
        if (i >= NHS4) return;
        float4 v = in[i];
        out[i] = make_float4(tf32rn(v.x), tf32rn(v.y), tf32rn(v.z), tf32rn(v.w));
    }
}

__global__ __launch_bounds__(256)
void round_wqkv_kernel(const float4* __restrict__ wq, const float4* __restrict__ wk,
                       const float4* __restrict__ wv, float4* __restrict__ wqkv)
{
    long base = ((long)blockIdx.x * 256 + threadIdx.x) * 4;
#pragma unroll
    for (int j = 0; j < 4; j++) {
        long i = base + j;
        if (i >= NWQKV4) return;
        float4 v;
        if (i < NQ4)            v = wq[i];
        else if (i < NQ4 + NK4) v = wk[i - NQ4];
        else                    v = wv[i - NQ4 - NK4];
        wqkv[i] = make_float4(tf32rn(v.x), tf32rn(v.y), tf32rn(v.z), tf32rn(v.w));
    }
}

__global__ __launch_bounds__(256)
void round_wo_kernel(const float4* __restrict__ in, float4* __restrict__ out)
{
    long base = ((long)blockIdx.x * 256 + threadIdx.x) * 4;
#pragma unroll
    for (int j = 0; j < 4; j++) {
        long i = base + j;
        if (i >= NQ4) return;
        float4 v = in[i];
        out[i] = make_float4(tf32rn(v.x), tf32rn(v.y), tf32rn(v.z), tf32rn(v.w));
    }
}

// =================================================================
// tf32 mma.sync GEMM, 128x128 CTA tile, 256 threads / 8 warps,
// warp tile 64x32, 3-stage cp.async, TWO CTAs resident per SM.
// C[m,n] = sum_k A[m,k]*B[n,k]; BK=32.
// Columns with n0 >= roundColStart get tf32-rounded in the epilogue.
// =================================================================
#define GSTRIDE 36
#define AT_FLOATS (128 * GSTRIDE)                // 4608
#define STAGE_FLOATS (2 * AT_FLOATS)             // A + B = 9216 floats = 36864 B
#define GEMM_STAGES 3
#define GEMM_SMEM (GEMM_STAGES * STAGE_FLOATS * 4)   // 110592 B per CTA

__global__ __launch_bounds__(256, 2)
void gemm_mma(const float* __restrict__ A, const float* __restrict__ B,
              float* __restrict__ C, int M, int N, int K, int roundColStart)
{
    extern __shared__ float sm[];

    const int tid = threadIdx.x;
    const int wid = tid >> 5;
    const int lane = tid & 31;
    const int g = lane >> 2;
    const int t = lane & 3;
    const int lr = lane & 7;
    const int lm = lane >> 3;
    const int wm = wid & 1;          // 2 m-groups of 64 rows
    const int wn = wid >> 1;         // 4 n-groups of 32 cols
    const int m0 = blockIdx.y * 128;
    const int n0 = blockIdx.x * 128;

    const float* Ag = A + (size_t)m0 * K;
    const float* Bg = B + (size_t)n0 * K;

    auto load_stage = [&](int kt, int slot) {
        float* As = sm + slot * STAGE_FLOATS;
        float* Bs = As + AT_FLOATS;
        const float* ap = Ag + kt * 32;
        const float* bp = Bg + kt * 32;
#pragma unroll
        for (int r = 0; r < 4; r++) {            // A: 1024 float4 chunks
            int c = r * 256 + tid;
            int row = c >> 3;
            int c4  = (c & 7) * 4;
            cp_async16(sa(As + row * GSTRIDE + c4), ap + (size_t)row * K + c4);
        }
#pragma unroll
        for (int r = 0; r < 4; r++) {            // B: 1024 float4 chunks
            int c = r * 256 + tid;
            int row = c >> 3;
            int c4  = (c & 7) * 4;
            cp_async16(sa(Bs + row * GSTRIDE + c4), bp + (size_t)row * K + c4);
        }
        cp_commit();
    };

    float d[4][4][4];
#pragma unroll
    for (int mi = 0; mi < 4; mi++)
#pragma unroll
        for (int ni = 0; ni < 4; ni++)
#pragma unroll
            for (int r = 0; r < 4; r++) d[mi][ni][r] = 0.0f;

    const uint32_t aoff = (uint32_t)(((wm * 64 + (lm & 1) * 8 + lr) * GSTRIDE
                                      + (lm >> 1) * 4) * 4);
    const uint32_t boff = (uint32_t)(((wn * 32 + (lm >> 1) * 8 + lr) * GSTRIDE
                                      + (lm & 1) * 4) * 4);

    const int NT = K / 32;
    load_stage(0, 0);
    load_stage(1, 1);

    int slot = 0;
    for (int kt = 0; kt < NT; kt++) {
        if (kt + 1 < NT) cp_wait<1>();
        else             cp_wait<0>();
        __syncthreads();

        if (kt + 2 < NT) {
            int ps = slot + 2; if (ps >= GEMM_STAGES) ps -= GEMM_STAGES;
            load_stage(kt + 2, ps);
        }

        const uint32_t As = sa(sm + slot * STAGE_FLOATS);
        const uint32_t Bs = As + AT_FLOATS * 4;

#pragma unroll
        for (int kk = 0; kk < 4; kk++) {
            uint32_t a[4][4];
#pragma unroll
            for (int mi = 0; mi < 4; mi++)
                ldsm4(a[mi][0], a[mi][1], a[mi][2], a[mi][3],
                      As + aoff + (uint32_t)((mi * 16 * GSTRIDE + kk * 8) * 4));
#pragma unroll
            for (int p = 0; p < 2; p++) {
                uint32_t b0, b1, b2, b3;
                ldsm4(b0, b1, b2, b3,
                      Bs + boff + (uint32_t)((p * 16 * GSTRIDE + kk * 8) * 4));
                uint32_t bf0[2] = {b0, b1};
                uint32_t bf1[2] = {b2, b3};
#pragma unroll
                for (int mi = 0; mi < 4; mi++) {
                    mma_tf32(d[mi][2*p],     a[mi], bf0);
                    mma_tf32(d[mi][2*p + 1], a[mi], bf1);
                }
            }
        }
        if (++slot == GEMM_STAGES) slot = 0;
    }

    // ---- epilogue (coalesced; optional tf32 rounding) ----
    const bool rnd = (n0 >= roundColStart);
#pragma unroll
    for (int mi = 0; mi < 4; mi++) {
        const int r0 = m0 + wm * 64 + mi * 16 + g;
        float* c0p = C + (size_t)r0 * N + n0 + wn * 32;
        float* c1p = c0p + (size_t)8 * N;
        if (rnd) {
#pragma unroll
            for (int ni = 0; ni < 4; ni++) {
                *(float2*)(c0p + ni * 8 + t * 2) =
                    make_float2(tf32rn(d[mi][ni][0]), tf32rn(d[mi][ni][1]));
                *(float2*)(c1p + ni * 8 + t * 2) =
                    make_float2(tf32rn(d[mi][ni][2]), tf32rn(d[mi][ni][3]));
            }
        } else {
#pragma unroll
            for (int ni = 0; ni < 4; ni++) {
                *(float2*)(c0p + ni * 8 + t * 2) = make_float2(d[mi][ni][0], d[mi][ni][1]);
                *(float2*)(c1p + ni * 8 + t * 2) = make_float2(d[mi][ni][2], d[mi][ni][3]);
            }
        }
    }
}

// =================================================================
// Fused RoPE for Q (slots 0-31, scale qscale) and K (slots 32-39).
// In place on g_qkv; output tf32-rounded.
// =================================================================
__global__ __launch_bounds__(256)
void rope_qk_kernel(float* __restrict__ qkv, const float* __restrict__ cosb,
                    const float* __restrict__ sinb, float qscale)
{
    long idx = (long)blockIdx.x * blockDim.x + threadIdx.x;
    long total = (long)TOKENS * (NH + NKV) * 64;
    if (idx >= total) return;
    int d = (int)(idx & 63);
    long t2 = idx >> 6;
    int slot = (int)(t2 % (NH + NKV));
    long tok = t2 / (NH + NKV);
    float scale = (slot < NH) ? qscale : 1.0f;
    int off = (slot < NH) ? slot * HD : QROW + (slot - NH) * HD;
    float* row = qkv + tok * QKVW + off;
    float c0 = cosb[tok * HD + d];
    float s0 = sinb[tok * HD + d];
    float c1 = cosb[tok * HD + d + 64];
    float s1 = sinb[tok * HD + d + 64];
    float a = row[d];
    float b = row[d + 64];
    row[d]      = tf32rn((a * c0 - b * s0) * scale);
    row[d + 64] = tf32rn((b * c1 + a * s1) * scale);
}

// =================================================================
// Tensor-core flash attention (causal, GQA 4:1), tf32 mma.sync.
// ldmatrix for Q/K fragments; scalar conflict-free loads for P/V.
// K and V read from fused qkv (token stride 6144), V row-major.
// CTA: 128 queries x 1 head; 8 warps x 16 query rows; key tile 64.
// =================================================================
#define AKS 132
#define AVSTR 136
#define APS 68
#define KS_FLOATS (64 * AKS)
#define VS_FLOATS (64 * AVSTR)
#define STG_FLOATS (KS_FLOATS + VS_FLOATS)
#define PS_OFF (2 * STG_FLOATS)
#define ATTN_SMEM ((PS_OFF + 128 * APS) * 4)  // 172032 B

__global__ __launch_bounds__(256, 1)
void attn_mma(const float* __restrict__ QKV, float* __restrict__ O)
{
    extern __shared__ float sm[];

    const int tid = threadIdx.x;
    const int wid = tid >> 5;
    const int lane = tid & 31;
    const int g = lane >> 2;
    const int t = lane & 3;
    const int lr = lane & 7;
    const int lm = lane >> 3;

    const int bh = blockIdx.y;
    const int b   = bh >> 5;
    const int h   = bh & 31;
    const int kvh = h >> 2;
    const int qt  = (int)(gridDim.x - 1 - blockIdx.x);
    const int q0  = qt * 128;

    const float* Qb = QKV + (size_t)b * SEQ * QKVW + h * HD;
    const float* Kb = QKV + (size_t)b * SEQ * QKVW + QROW + kvh * HD;
    const float* Vb = QKV + (size_t)b * SEQ * QKVW + VCOL0 + kvh * HD;

    // ---- stage Q into smem (stage-0 region), fragments via ldmatrix ----
    {
#pragma unroll
        for (int it = 0; it < 16; it++) {
            int idx = it * 256 + tid;
            int row = idx >> 5;
            int c4  = (idx & 31) * 4;
            cp_async16(sa(sm + row * AKS + c4),
                       Qb + (size_t)(q0 + row) * QKVW + c4);
        }
        cp_commit();
        cp_wait<0>();
        __syncthreads();
    }

    uint32_t qa[16][4];
    {
        const uint32_t qoff = sa(sm) +
            (uint32_t)(((wid * 16 + (lm & 1) * 8 + lr) * AKS + (lm >> 1) * 4) * 4);
#pragma unroll
        for (int kk = 0; kk < 16; kk++)
            ldsm4(qa[kk][0], qa[kk][1], qa[kk][2], qa[kk][3], qoff + kk * 32);
    }
    __syncthreads();

    const int qbase = q0 + wid * 16;

    float m0r = -1e30f, m1r = -1e30f, l0r = 0.0f, l1r = 0.0f;
    float oa[16][4];
#pragma unroll
    for (int ni = 0; ni < 16; ni++)
#pragma unroll
        for (int r = 0; r < 4; r++) oa[ni][r] = 0.0f;

    const int nkt = qt * 2 + 2;

    auto load_kv = [&](int kt, int st) {
        float* Ks = sm + st * STG_FLOATS;
        float* Vs = Ks + KS_FLOATS;
        const int k0 = kt * 64;
#pragma unroll
        for (int it = 0; it < 8; it++) {
            int idx = it * 256 + tid;
            int row = idx >> 5;
            int c4  = (idx & 31) * 4;
            cp_async16(sa(Ks + row * AKS + c4),
                       Kb + (size_t)(k0 + row) * QKVW + c4);
        }
#pragma unroll
        for (int it = 0; it < 8; it++) {
            int idx = it * 256 + tid;
            int row = idx >> 5;
            int c4  = (idx & 31) * 4;
            cp_async16(sa(Vs + row * AVSTR + c4),
                       Vb + (size_t)(k0 + row) * QKVW + c4);
        }
        cp_commit();
    };

    load_kv(0, 0);
    load_kv(1, 1);

    const uint32_t kboff = (uint32_t)((((lm >> 1) * 8 + lr) * AKS + (lm & 1) * 4) * 4);

    for (int kt = 0; kt < nkt; kt++) {
        const int st = kt & 1;
        const int k0 = kt * 64;
        if (kt + 1 < nkt) cp_wait<1>();
        else              cp_wait<0>();
        __syncthreads();

        const uint32_t KsA = sa(sm + st * STG_FLOATS);
        const float* Vs = sm + st * STG_FLOATS + KS_FLOATS;

        // ---- scores S = Q K^T (p-outer to minimize live temps) ----
        float sc[8][4];
#pragma unroll
        for (int ni = 0; ni < 8; ni++)
#pragma unroll
            for (int r = 0; r < 4; r++) sc[ni][r] = 0.0f;

#pragma unroll
        for (int p = 0; p < 4; p++) {
#pragma unroll
            for (int kk = 0; kk < 16; kk++) {
                uint32_t b0, b1, b2, b3;
                ldsm4(b0, b1, b2, b3,
                      KsA + kboff + (uint32_t)((p * 16 * AKS + kk * 8) * 4));
                uint32_t bf0[2] = {b0, b1};
                uint32_t bf1[2] = {b2, b3};
                mma_tf32(sc[2*p],     qa[kk], bf0);
                mma_tf32(sc[2*p + 1], qa[kk], bf1);
            }
        }

        // ---- causal mask ----
        if (k0 + 63 > qbase) {
#pragma unroll
            for (int ni = 0; ni < 8; ni++) {
                int c0 = k0 + ni * 8 + 2 * t;
                int r0 = qbase + g;
                if (c0 > r0)     sc[ni][0] = -1e30f;
                if (c0 + 1 > r0) sc[ni][1] = -1e30f;
                if (c0 > r0 + 8)     sc[ni][2] = -1e30f;
                if (c0 + 1 > r0 + 8) sc[ni][3] = -1e30f;
            }
        }

        // ---- online softmax ----
        float mx0 = -1e30f, mx1 = -1e30f;
#pragma unroll
        for (int ni = 0; ni < 8; ni++) {
            mx0 = fmaxf(mx0, fmaxf(sc[ni][0], sc[ni][1]));
            mx1 = fmaxf(mx1, fmaxf(sc[ni][2], sc[ni][3]));
        }
        mx0 = fmaxf(mx0, __shfl_xor_sync(0xffffffffu, mx0, 1));
        mx0 = fmaxf(mx0, __shfl_xor_sync(0xffffffffu, mx0, 2));
        mx1 = fmaxf(mx1, __shfl_xor_sync(0xffffffffu, mx1, 1));
        mx1 = fmaxf(mx1, __shfl_xor_sync(0xffffffffu, mx1, 2));

        float mn0 = fmaxf(m0r, mx0);
        float mn1 = fmaxf(m1r, mx1);
        float cr0 = ex2(m0r - mn0);
        float cr1 = ex2(m1r - mn1);
        m0r = mn0; m1r = mn1;

        float rs0 = 0.0f, rs1 = 0.0f;
        float* pw0 = sm + PS_OFF + (wid * 16 + g) * APS;
        float* pw1 = pw0 + 8 * APS;
#pragma unroll
        for (int ni = 0; ni < 8; ni++) {
            float p0 = ex2(sc[ni][0] - mn0);
            float p1 = ex2(sc[ni][1] - mn0);
            float p2 = ex2(sc[ni][2] - mn1);
            float p3 = ex2(sc[ni][3] - mn1);
            rs0 += p0 + p1;
            rs1 += p2 + p3;
            *(float2*)(pw0 + ni * 8 + 2 * t) = make_float2(tf32rn(p0), tf32rn(p1));
            *(float2*)(pw1 + ni * 8 + 2 * t) = make_float2(tf32rn(p2), tf32rn(p3));
        }
        rs0 += __shfl_xor_sync(0xffffffffu, rs0, 1);
        rs0 += __shfl_xor_sync(0xffffffffu, rs0, 2);
        rs1 += __shfl_xor_sync(0xffffffffu, rs1, 1);
        rs1 += __shfl_xor_sync(0xffffffffu, rs1, 2);
        l0r = l0r * cr0 + rs0;
        l1r = l1r * cr1 + rs1;

#pragma unroll
        for (int ni = 0; ni < 16; ni++) {
            oa[ni][0] *= cr0; oa[ni][1] *= cr0;
            oa[ni][2] *= cr1; oa[ni][3] *= cr1;
        }
        __syncwarp();

        // ---- O += P V : scalar conflict-free fragment loads ----
#pragma unroll
        for (int kk = 0; kk < 8; kk++) {
            uint32_t a[4];
            const float* ap = sm + PS_OFF + (wid * 16 + g) * APS + kk * 8 + t;
            a[0] = __float_as_uint(ap[0]);
            a[1] = __float_as_uint(ap[8 * APS]);
            a[2] = __float_as_uint(ap[4]);
            a[3] = __float_as_uint(ap[8 * APS + 4]);
#pragma unroll
            for (int ni = 0; ni < 16; ni++) {
                uint32_t bfr[2];
                const float* bp = Vs + (kk * 8 + t) * AVSTR + ni * 8 + g;
                bfr[0] = __float_as_uint(bp[0]);
                bfr[1] = __float_as_uint(bp[4 * AVSTR]);
                mma_tf32(oa[ni], a, bfr);
            }
        }
        __syncthreads();
        if (kt + 2 < nkt) load_kv(kt + 2, st);
    }

    // ---- epilogue: O / l, tf32-rounded for the O-projection ----
    float inv0 = 1.0f / l0r;
    float inv1 = 1.0f / l1r;
    float* o0 = O + (size_t)((size_t)b * SEQ + qbase + g) * QROW + h * HD;
    float* o1 = o0 + (size_t)8 * QROW;
#pragma unroll
    for (int ni = 0; ni < 16; ni++) {
        *(float2*)(o0 + ni * 8 + 2 * t) =
            make_float2(tf32rn(oa[ni][0] * inv0), tf32rn(oa[ni][1] * inv0));
        *(float2*)(o1 + ni * 8 + 2 * t) =
            make_float2(tf32rn(oa[ni][2] * inv1), tf32rn(oa[ni][3] * inv1));
    }
}

// =================================================================
extern "C" void kernel_launch(void* const* d_in, const int* in_sizes, int n_in,
                              void* d_out, int out_size)
{
    const float* hs   = (const float*)d_in[0];
    const float* cosb = (const float*)d_in[1];
    const float* sinb = (const float*)d_in[2];
    const float* wq   = (const float*)d_in[3];
    const float* wk   = (const float*)d_in[4];
    const float* wv   = (const float*)d_in[5];
    const float* wo   = (const float*)d_in[6];
    float* out = (float*)d_out;

    float *qkv, *attn, *hsc, *wqkv, *woc;
    cudaGetSymbolAddress((void**)&qkv,  g_qkv);
    cudaGetSymbolAddress((void**)&attn, g_attn);
    cudaGetSymbolAddress((void**)&hsc,  g_hsc);
    cudaGetSymbolAddress((void**)&wqkv, g_wqkv);
    cudaGetSymbolAddress((void**)&woc,  g_woc);

    cudaFuncSetAttribute(gemm_mma, cudaFuncAttributeMaxDynamicSharedMemorySize, GEMM_SMEM);
    cudaFuncSetAttribute(attn_mma, cudaFuncAttributeMaxDynamicSharedMemorySize, ATTN_SMEM);

    // L0-L2: tf32 rounding (hs, wq|wk|wv, wo)
    round_hs_kernel<<<(unsigned)((NHS4 + 1023) / 1024), 256>>>(
        (const float4*)hs, (float4*)hsc);
    round_wqkv_kernel<<<(unsigned)((NWQKV4 + 1023) / 1024), 256>>>(
        (const float4*)wq, (const float4*)wk, (const float4*)wv, (float4*)wqkv);
    round_wo_kernel<<<(unsigned)((NQ4 + 1023) / 1024), 256>>>(
        (const float4*)wo, (float4*)woc);

    // L3: fused QKV projection (2 CTAs/SM; profiled at launch index 3)
    gemm_mma<<<dim3(QKVW / 128, TOKENS / 128), 256, GEMM_SMEM>>>(
        hsc, wqkv, qkv, TOKENS, QKVW, HID, VCOL0);

    // L4: fused RoPE Q+K (Q scale folds 1/sqrt(128)*log2(e))
    const float qscale = 0.08838834764831845f * 1.4426950408889634f;
    rope_qk_kernel<<<(TOKENS * (NH + NKV) * 64) / 256, 256>>>(qkv, cosb, sinb, qscale);

    // L5: flash attention
    attn_mma<<<dim3(SEQ / 128, BATCH * NH), 256, ATTN_SMEM>>>(qkv, attn);

    // L6: output projection (no epilogue rounding)
    gemm_mma<<<dim3(HID / 128, TOKENS / 128), 256, GEMM_SMEM>>>(
        attn, woc, out, TOKENS, HID, QROW, 1 << 30);
}

// round 12
// speedup vs baseline: 1.2598x; 1.0100x over previous
#include <cuda_runtime.h>
#include <cuda_bf16.h>
#include <math.h>
#include <cstdint>

// Problem constants
#define BATCH 2
#define SEQ   2048
#define HID   4096
#define NH    32
#define NKV   8
#define HD    128
#define TOKENS (BATCH*SEQ)          // 4096
#define QROW (NH*HD)                // 4096
#define KROW (NKV*HD)               // 1024
#define QKVW (QROW + 2*KROW)        // 6144
#define VCOL0 (QROW + KROW)         // 5120 : first V column in fused qkv

// ---------------- scratch (no cudaMalloc allowed) ----------------
__device__ float g_qkv[(size_t)TOKENS * QKVW];   // q|k|v per token
__device__ float g_attn[(size_t)TOKENS * QROW];
__device__ float g_hsc[(size_t)TOKENS * HID];
__device__ float g_wqkv[(size_t)QKVW * HID];
__device__ float g_woc[(size_t)HID * QROW];

// ---------------- helpers ----------------
__device__ __forceinline__ uint32_t sa(const void* p) {
    return (uint32_t)__cvta_generic_to_shared(p);
}
__device__ __forceinline__ void cp_async16(uint32_t s, const void* g) {
    asm volatile("cp.async.cg.shared.global [%0], [%1], 16;" :: "r"(s), "l"(g));
}
__device__ __forceinline__ void cp_commit() {
    asm volatile("cp.async.commit_group;" ::: "memory");
}
template <int N>
__device__ __forceinline__ void cp_wait() {
    asm volatile("cp.async.wait_group %0;" :: "n"(N) : "memory");
}
__device__ __forceinline__ void ldsm4(uint32_t& r0, uint32_t& r1, uint32_t& r2,
                                      uint32_t& r3, uint32_t addr) {
    asm volatile("ldmatrix.sync.aligned.m8n8.x4.shared.b16 {%0,%1,%2,%3}, [%4];"
                 : "=r"(r0), "=r"(r1), "=r"(r2), "=r"(r3) : "r"(addr));
}
__device__ __forceinline__ void mma_tf32(float* d, const uint32_t* a, const uint32_t* b) {
    asm volatile(
        "mma.sync.aligned.m16n8k8.row.col.f32.tf32.tf32.f32 "
        "{%0,%1,%2,%3}, {%4,%5,%6,%7}, {%8,%9}, {%0,%1,%2,%3};"
        : "+f"(d[0]), "+f"(d[1]), "+f"(d[2]), "+f"(d[3])
        : "r"(a[0]), "r"(a[1]), "r"(a[2]), "r"(a[3]), "r"(b[0]), "r"(b[1]));
}
__device__ __forceinline__ float tf32rn(float x) {
    uint32_t u;
    asm("cvt.rn.tf32.f32 %0, %1;" : "=r"(u) : "f"(x));
    return __uint_as_float(u);
}
__device__ __forceinline__ float ex2(float x) {
    float y;
    asm("ex2.approx.ftz.f32 %0, %1;" : "=f"(y) : "f"(x));
    return y;
}
__device__ __forceinline__ float4 rnd4(float4 v) {
    return make_float4(tf32rn(v.x), tf32rn(v.y), tf32rn(v.z), tf32rn(v.w));
}

// =================================================================
// L0: fused rounding of hs + all weights in ONE kernel.
// Per-block job routing with compile-time boundaries. Every segment
// size is an exact multiple of 1024 float4 -> no bounds checks.
// Each thread: 4 independent LDG.128, 4 STG.128 (MLP=4).
// =================================================================
#define NHS4 ((long)TOKENS * HID / 4)    // 4096*1024
#define NQ4  ((long)QROW * HID / 4)      // 4096*1024
#define NK4  ((long)KROW * HID / 4)      // 1024*1024
#define B_HS 4096
#define B_W  4096
#define B_K  1024
#define ROUND_BLOCKS (B_HS + B_W + 2*B_K + B_W)   // 14336

__global__ __launch_bounds__(256)
void round_all_kernel(const float4* __restrict__ hs, const float4* __restrict__ wq,
                      const float4* __restrict__ wk, const float4* __restrict__ wv,
                      const float4* __restrict__ wo,
                      float4* __restrict__ hsc, float4* __restrict__ wqkv,
                      float4* __restrict__ woc)
{
    int b = blockIdx.x;
    const float4* src;
    float4* dst;
    if (b < B_HS)                       { src = hs; dst = hsc; }
    else if (b < B_HS + B_W)            { b -= B_HS;           src = wq; dst = wqkv; }
    else if (b < B_HS + B_W + B_K)      { b -= B_HS + B_W;     src = wk; dst = wqkv + NQ4; }
    else if (b < B_HS + B_W + 2*B_K)    { b -= B_HS + B_W + B_K; src = wv; dst = wqkv + NQ4 + NK4; }
    else                                { b -= B_HS + B_W + 2*B_K; src = wo; dst = woc; }

    long i = (long)b * 1024 + threadIdx.x;
    float4 v0 = src[i];
    float4 v1 = src[i + 256];
    float4 v2 = src[i + 512];
    float4 v3 = src[i + 768];
    dst[i]       = rnd4(v0);
    dst[i + 256] = rnd4(v1);
    dst[i + 512] = rnd4(v2);
    dst[i + 768] = rnd4(v3);
}

// =================================================================
// tf32 mma.sync GEMM, 128x128 CTA tile, 256 threads / 8 warps,
// warp tile 64x32, 3-stage cp.async, TWO CTAs resident per SM.
// C[m,n] = sum_k A[m,k]*B[n,k]; BK=32.
// Columns with n0 >= roundColStart get tf32-rounded in the epilogue.
// =================================================================
#define GSTRIDE 36
#define AT_FLOATS (128 * GSTRIDE)                // 4608
#define STAGE_FLOATS (2 * AT_FLOATS)             // A + B = 9216 floats = 36864 B
#define GEMM_STAGES 3
#define GEMM_SMEM (GEMM_STAGES * STAGE_FLOATS * 4)   // 110592 B per CTA

__global__ __launch_bounds__(256, 2)
void gemm_mma(const float* __restrict__ A, const float* __restrict__ B,
              float* __restrict__ C, int M, int N, int K, int roundColStart)
{
    extern __shared__ float sm[];

    const int tid = threadIdx.x;
    const int wid = tid >> 5;
    const int lane = tid & 31;
    const int g = lane >> 2;
    const int t = lane & 3;
    const int lr = lane & 7;
    const int lm = lane >> 3;
    const int wm = wid & 1;          // 2 m-groups of 64 rows
    const int wn = wid >> 1;         // 4 n-groups of 32 cols
    const int m0 = blockIdx.y * 128;
    const int n0 = blockIdx.x * 128;

    const float* Ag = A + (size_t)m0 * K;
    const float* Bg = B + (size_t)n0 * K;

    auto load_stage = [&](int kt, int slot) {
        float* As = sm + slot * STAGE_FLOATS;
        float* Bs = As + AT_FLOATS;
        const float* ap = Ag + kt * 32;
        const float* bp = Bg + kt * 32;
#pragma unroll
        for (int r = 0; r < 4; r++) {            // A: 1024 float4 chunks
            int c = r * 256 + tid;
            int row = c >> 3;
            int c4  = (c & 7) * 4;
            cp_async16(sa(As + row * GSTRIDE + c4), ap + (size_t)row * K + c4);
        }
#pragma unroll
        for (int r = 0; r < 4; r++) {            // B: 1024 float4 chunks
            int c = r * 256 + tid;
            int row = c >> 3;
            int c4  = (c & 7) * 4;
            cp_async16(sa(Bs + row * GSTRIDE + c4), bp + (size_t)row * K + c4);
        }
        cp_commit();
    };

    float d[4][4][4];
#pragma unroll
    for (int mi = 0; mi < 4; mi++)
#pragma unroll
        for (int ni = 0; ni < 4; ni++)
#pragma unroll
            for (int r = 0; r < 4; r++) d[mi][ni][r] = 0.0f;

    const uint32_t aoff = (uint32_t)(((wm * 64 + (lm & 1) * 8 + lr) * GSTRIDE
                                      + (lm >> 1) * 4) * 4);
    const uint32_t boff = (uint32_t)(((wn * 32 + (lm >> 1) * 8 + lr) * GSTRIDE
                                      + (lm & 1) * 4) * 4);

    const int NT = K / 32;
    load_stage(0, 0);
    load_stage(1, 1);

    int slot = 0;
    for (int kt = 0; kt < NT; kt++) {
        if (kt + 1 < NT) cp_wait<1>();
        else             cp_wait<0>();
        __syncthreads();

        if (kt + 2 < NT) {
            int ps = slot + 2; if (ps >= GEMM_STAGES) ps -= GEMM_STAGES;
            load_stage(kt + 2, ps);
        }

        const uint32_t As = sa(sm + slot * STAGE_FLOATS);
        const uint32_t Bs = As + AT_FLOATS * 4;

#pragma unroll
        for (int kk = 0; kk < 4; kk++) {
            uint32_t a[4][4];
#pragma unroll
            for (int mi = 0; mi < 4; mi++)
                ldsm4(a[mi][0], a[mi][1], a[mi][2], a[mi][3],
                      As + aoff + (uint32_t)((mi * 16 * GSTRIDE + kk * 8) * 4));
#pragma unroll
            for (int p = 0; p < 2; p++) {
                uint32_t b0, b1, b2, b3;
                ldsm4(b0, b1, b2, b3,
                      Bs + boff + (uint32_t)((p * 16 * GSTRIDE + kk * 8) * 4));
                uint32_t bf0[2] = {b0, b1};
                uint32_t bf1[2] = {b2, b3};
#pragma unroll
                for (int mi = 0; mi < 4; mi++) {
                    mma_tf32(d[mi][2*p],     a[mi], bf0);
                    mma_tf32(d[mi][2*p + 1], a[mi], bf1);
                }
            }
        }
        if (++slot == GEMM_STAGES) slot = 0;
    }

    // ---- epilogue (coalesced; optional tf32 rounding) ----
    const bool rnd = (n0 >= roundColStart);
#pragma unroll
    for (int mi = 0; mi < 4; mi++) {
        const int r0 = m0 + wm * 64 + mi * 16 + g;
        float* c0p = C + (size_t)r0 * N + n0 + wn * 32;
        float* c1p = c0p + (size_t)8 * N;
        if (rnd) {
#pragma unroll
            for (int ni = 0; ni < 4; ni++) {
                *(float2*)(c0p + ni * 8 + t * 2) =
                    make_float2(tf32rn(d[mi][ni][0]), tf32rn(d[mi][ni][1]));
                *(float2*)(c1p + ni * 8 + t * 2) =
                    make_float2(tf32rn(d[mi][ni][2]), tf32rn(d[mi][ni][3]));
            }
        } else {
#pragma unroll
            for (int ni = 0; ni < 4; ni++) {
                *(float2*)(c0p + ni * 8 + t * 2) = make_float2(d[mi][ni][0], d[mi][ni][1]);
                *(float2*)(c1p + ni * 8 + t * 2) = make_float2(d[mi][ni][2], d[mi][ni][3]);
            }
        }
    }
}

// =================================================================
// Fused RoPE for Q (slots 0-31, scale qscale) and K (slots 32-39).
// In place on g_qkv; output tf32-rounded.
// =================================================================
__global__ __launch_bounds__(256)
void rope_qk_kernel(float* __restrict__ qkv, const float* __restrict__ cosb,
                    const float* __restrict__ sinb, float qscale)
{
    long idx = (long)blockIdx.x * blockDim.x + threadIdx.x;
    long total = (long)TOKENS * (NH + NKV) * 64;
    if (idx >= total) return;
    int d = (int)(idx & 63);
    long t2 = idx >> 6;
    int slot = (int)(t2 % (NH + NKV));
    long tok = t2 / (NH + NKV);
    float scale = (slot < NH) ? qscale : 1.0f;
    int off = (slot < NH) ? slot * HD : QROW + (slot - NH) * HD;
    float* row = qkv + tok * QKVW + off;
    float c0 = cosb[tok * HD + d];
    float s0 = sinb[tok * HD + d];
    float c1 = cosb[tok * HD + d + 64];
    float s1 = sinb[tok * HD + d + 64];
    float a = row[d];
    float b = row[d + 64];
    row[d]      = tf32rn((a * c0 - b * s0) * scale);
    row[d + 64] = tf32rn((b * c1 + a * s1) * scale);
}

// =================================================================
// Tensor-core flash attention (causal, GQA 4:1), tf32 mma.sync.
// ldmatrix for Q/K fragments; scalar conflict-free loads for P/V.
// K and V read from fused qkv (token stride 6144), V row-major.
// CTA: 128 queries x 1 head; 8 warps x 16 query rows; key tile 64.
// =================================================================
#define AKS 132
#define AVSTR 136
#define APS 68
#define KS_FLOATS (64 * AKS)
#define VS_FLOATS (64 * AVSTR)
#define STG_FLOATS (KS_FLOATS + VS_FLOATS)
#define PS_OFF (2 * STG_FLOATS)
#define ATTN_SMEM ((PS_OFF + 128 * APS) * 4)  // 172032 B

__global__ __launch_bounds__(256, 1)
void attn_mma(const float* __restrict__ QKV, float* __restrict__ O)
{
    extern __shared__ float sm[];

    const int tid = threadIdx.x;
    const int wid = tid >> 5;
    const int lane = tid & 31;
    const int g = lane >> 2;
    const int t = lane & 3;
    const int lr = lane & 7;
    const int lm = lane >> 3;

    const int bh = blockIdx.y;
    const int b   = bh >> 5;
    const int h   = bh & 31;
    const int kvh = h >> 2;
    const int qt  = (int)(gridDim.x - 1 - blockIdx.x);
    const int q0  = qt * 128;

    const float* Qb = QKV + (size_t)b * SEQ * QKVW + h * HD;
    const float* Kb = QKV + (size_t)b * SEQ * QKVW + QROW + kvh * HD;
    const float* Vb = QKV + (size_t)b * SEQ * QKVW + VCOL0 + kvh * HD;

    // ---- stage Q into smem (stage-0 region), fragments via ldmatrix ----
    {
#pragma unroll
        for (int it = 0; it < 16; it++) {
            int idx = it * 256 + tid;
            int row = idx >> 5;
            int c4  = (idx & 31) * 4;
            cp_async16(sa(sm + row * AKS + c4),
                       Qb + (size_t)(q0 + row) * QKVW + c4);
        }
        cp_commit();
        cp_wait<0>();
        __syncthreads();
    }

    uint32_t qa[16][4];
    {
        const uint32_t qoff = sa(sm) +
            (uint32_t)(((wid * 16 + (lm & 1) * 8 + lr) * AKS + (lm >> 1) * 4) * 4);
#pragma unroll
        for (int kk = 0; kk < 16; kk++)
            ldsm4(qa[kk][0], qa[kk][1], qa[kk][2], qa[kk][3], qoff + kk * 32);
    }
    __syncthreads();

    const int qbase = q0 + wid * 16;

    float m0r = -1e30f, m1r = -1e30f, l0r = 0.0f, l1r = 0.0f;
    float oa[16][4];
#pragma unroll
    for (int ni = 0; ni < 16; ni++)
#pragma unroll
        for (int r = 0; r < 4; r++) oa[ni][r] = 0.0f;

    const int nkt = qt * 2 + 2;

    auto load_kv = [&](int kt, int st) {
        float* Ks = sm + st * STG_FLOATS;
        float* Vs = Ks + KS_FLOATS;
        const int k0 = kt * 64;
#pragma unroll
        for (int it = 0; it < 8; it++) {
            int idx = it * 256 + tid;
            int row = idx >> 5;
            int c4  = (idx & 31) * 4;
            cp_async16(sa(Ks + row * AKS + c4),
                       Kb + (size_t)(k0 + row) * QKVW + c4);
        }
#pragma unroll
        for (int it = 0; it < 8; it++) {
            int idx = it * 256 + tid;
            int row = idx >> 5;
            int c4  = (idx & 31) * 4;
            cp_async16(sa(Vs + row * AVSTR + c4),
                       Vb + (size_t)(k0 + row) * QKVW + c4);
        }
        cp_commit();
    };

    load_kv(0, 0);
    load_kv(1, 1);

    const uint32_t kboff = (uint32_t)((((lm >> 1) * 8 + lr) * AKS + (lm & 1) * 4) * 4);

    for (int kt = 0; kt < nkt; kt++) {
        const int st = kt & 1;
        const int k0 = kt * 64;
        if (kt + 1 < nkt) cp_wait<1>();
        else              cp_wait<0>();
        __syncthreads();

        const uint32_t KsA = sa(sm + st * STG_FLOATS);
        const float* Vs = sm + st * STG_FLOATS + KS_FLOATS;

        // ---- scores S = Q K^T (p-outer to minimize live temps) ----
        float sc[8][4];
#pragma unroll
        for (int ni = 0; ni < 8; ni++)
#pragma unroll
            for (int r = 0; r < 4; r++) sc[ni][r] = 0.0f;

#pragma unroll
        for (int p = 0; p < 4; p++) {
#pragma unroll
            for (int kk = 0; kk < 16; kk++) {
                uint32_t b0, b1, b2, b3;
                ldsm4(b0, b1, b2, b3,
                      KsA + kboff + (uint32_t)((p * 16 * AKS + kk * 8) * 4));
                uint32_t bf0[2] = {b0, b1};
                uint32_t bf1[2] = {b2, b3};
                mma_tf32(sc[2*p],     qa[kk], bf0);
                mma_tf32(sc[2*p + 1], qa[kk], bf1);
            }
        }

        // ---- causal mask ----
        if (k0 + 63 > qbase) {
#pragma unroll
            for (int ni = 0; ni < 8; ni++) {
                int c0 = k0 + ni * 8 + 2 * t;
                int r0 = qbase + g;
                if (c0 > r0)     sc[ni][0] = -1e30f;
                if (c0 + 1 > r0) sc[ni][1] = -1e30f;
                if (c0 > r0 + 8)     sc[ni][2] = -1e30f;
                if (c0 + 1 > r0 + 8) sc[ni][3] = -1e30f;
            }
        }

        // ---- online softmax ----
        float mx0 = -1e30f, mx1 = -1e30f;
#pragma unroll
        for (int ni = 0; ni < 8; ni++) {
            mx0 = fmaxf(mx0, fmaxf(sc[ni][0], sc[ni][1]));
            mx1 = fmaxf(mx1, fmaxf(sc[ni][2], sc[ni][3]));
        }
        mx0 = fmaxf(mx0, __shfl_xor_sync(0xffffffffu, mx0, 1));
        mx0 = fmaxf(mx0, __shfl_xor_sync(0xffffffffu, mx0, 2));
        mx1 = fmaxf(mx1, __shfl_xor_sync(0xffffffffu, mx1, 1));
        mx1 = fmaxf(mx1, __shfl_xor_sync(0xffffffffu, mx1, 2));

        float mn0 = fmaxf(m0r, mx0);
        float mn1 = fmaxf(m1r, mx1);
        float cr0 = ex2(m0r - mn0);
        float cr1 = ex2(m1r - mn1);
        m0r = mn0; m1r = mn1;

        float rs0 = 0.0f, rs1 = 0.0f;
        float* pw0 = sm + PS_OFF + (wid * 16 + g) * APS;
        float* pw1 = pw0 + 8 * APS;
#pragma unroll
        for (int ni = 0; ni < 8; ni++) {
            float p0 = ex2(sc[ni][0] - mn0);
            float p1 = ex2(sc[ni][1] - mn0);
            float p2 = ex2(sc[ni][2] - mn1);
            float p3 = ex2(sc[ni][3] - mn1);
            rs0 += p0 + p1;
            rs1 += p2 + p3;
            *(float2*)(pw0 + ni * 8 + 2 * t) = make_float2(tf32rn(p0), tf32rn(p1));
            *(float2*)(pw1 + ni * 8 + 2 * t) = make_float2(tf32rn(p2), tf32rn(p3));
        }
        rs0 += __shfl_xor_sync(0xffffffffu, rs0, 1);
        rs0 += __shfl_xor_sync(0xffffffffu, rs0, 2);
        rs1 += __shfl_xor_sync(0xffffffffu, rs1, 1);
        rs1 += __shfl_xor_sync(0xffffffffu, rs1, 2);
        l0r = l0r * cr0 + rs0;
        l1r = l1r * cr1 + rs1;

#pragma unroll
        for (int ni = 0; ni < 16; ni++) {
            oa[ni][0] *= cr0; oa[ni][1] *= cr0;
            oa[ni][2] *= cr1; oa[ni][3] *= cr1;
        }
        __syncwarp();

        // ---- O += P V : scalar conflict-free fragment loads ----
#pragma unroll
        for (int kk = 0; kk < 8; kk++) {
            uint32_t a[4];
            const float* ap = sm + PS_OFF + (wid * 16 + g) * APS + kk * 8 + t;
            a[0] = __float_as_uint(ap[0]);
            a[1] = __float_as_uint(ap[8 * APS]);
            a[2] = __float_as_uint(ap[4]);
            a[3] = __float_as_uint(ap[8 * APS + 4]);
#pragma unroll
            for (int ni = 0; ni < 16; ni++) {
                uint32_t bfr[2];
                const float* bp = Vs + (kk * 8 + t) * AVSTR + ni * 8 + g;
                bfr[0] = __float_as_uint(bp[0]);
                bfr[1] = __float_as_uint(bp[4 * AVSTR]);
                mma_tf32(oa[ni], a, bfr);
            }
        }
        __syncthreads();
        if (kt + 2 < nkt) load_kv(kt + 2, st);
    }

    // ---- epilogue: O / l, tf32-rounded for the O-projection ----
    float inv0 = 1.0f / l0r;
    float inv1 = 1.0f / l1r;
    float* o0 = O + (size_t)((size_t)b * SEQ + qbase + g) * QROW + h * HD;
    float* o1 = o0 + (size_t)8 * QROW;
#pragma unroll
    for (int ni = 0; ni < 16; ni++) {
        *(float2*)(o0 + ni * 8 + 2 * t) =
            make_float2(tf32rn(oa[ni][0] * inv0), tf32rn(oa[ni][1] * inv0));
        *(float2*)(o1 + ni * 8 + 2 * t) =
            make_float2(tf32rn(oa[ni][2] * inv1), tf32rn(oa[ni][3] * inv1));
    }
}

// =================================================================
extern "C" void kernel_launch(void* const* d_in, const int* in_sizes, int n_in,
                              void* d_out, int out_size)
{
    const float* hs   = (const float*)d_in[0];
    const float* cosb = (const float*)d_in[1];
    const float* sinb = (const float*)d_in[2];
    const float* wq   = (const float*)d_in[3];
    const float* wk   = (const float*)d_in[4];
    const float* wv   = (const float*)d_in[5];
    const float* wo   = (const float*)d_in[6];
    float* out = (float*)d_out;

    float *qkv, *attn, *hsc, *wqkv, *woc;
    cudaGetSymbolAddress((void**)&qkv,  g_qkv);
    cudaGetSymbolAddress((void**)&attn, g_attn);
    cudaGetSymbolAddress((void**)&hsc,  g_hsc);
    cudaGetSymbolAddress((void**)&wqkv, g_wqkv);
    cudaGetSymbolAddress((void**)&woc,  g_woc);

    cudaFuncSetAttribute(gemm_mma, cudaFuncAttributeMaxDynamicSharedMemorySize, GEMM_SMEM);
    cudaFuncSetAttribute(attn_mma, cudaFuncAttributeMaxDynamicSharedMemorySize, ATTN_SMEM);

    // L0: fused tf32 rounding (hs + wq|wk|wv + wo), batched MLP=4
    round_all_kernel<<<ROUND_BLOCKS, 256>>>(
        (const float4*)hs, (const float4*)wq, (const float4*)wk,
        (const float4*)wv, (const float4*)wo,
        (float4*)hsc, (float4*)wqkv, (float4*)woc);

    // L1: fused QKV projection (2 CTAs/SM); V columns tf32-rounded
    gemm_mma<<<dim3(QKVW / 128, TOKENS / 128), 256, GEMM_SMEM>>>(
        hsc, wqkv, qkv, TOKENS, QKVW, HID, VCOL0);

    // L2: fused RoPE Q+K (Q scale folds 1/sqrt(128)*log2(e))
    const float qscale = 0.08838834764831845f * 1.4426950408889634f;
    rope_qk_kernel<<<(TOKENS * (NH + NKV) * 64) / 256, 256>>>(qkv, cosb, sinb, qscale);

    // L3: flash attention (profiled: launch index 3)
    attn_mma<<<dim3(SEQ / 128, BATCH * NH), 256, ATTN_SMEM>>>(qkv, attn);

    // L4: output projection (no epilogue rounding)
    gemm_mma<<<dim3(HID / 128, TOKENS / 128), 256, GEMM_SMEM>>>(
        attn, woc, out, TOKENS, HID, QROW, 1 << 30);
}